// round 3
// baseline (speedup 1.0000x reference)
#include <cuda_runtime.h>
#include <math.h>

#define Bsz 2
#define T 2048
#define D 1024
#define NH 16
#define HD 64
#define NT (Bsz*T)    /* 4096 rows */
#define DFF 4096

// ---------------- scratch (device globals; no allocation allowed) ----------------
__device__ float g_h [NT*D];
__device__ float g_q [NT*D];
__device__ float g_k [NT*D];
__device__ float g_v [NT*D];
__device__ float g_att[NT*D];
__device__ float g_x2[NT*D];
__device__ float g_h2[NT*D];
__device__ float g_f1[(size_t)NT*DFF];

// ---------------- LayerNorm: one block (256 thr) per row of 1024 ----------------
__global__ void __launch_bounds__(256) ln_kernel(const float* __restrict__ x,
                                                 const float* __restrict__ gam,
                                                 const float* __restrict__ bet,
                                                 float* __restrict__ out)
{
    int row = blockIdx.x;
    const float* xr = x + (size_t)row * D;
    float* orow     = out + (size_t)row * D;
    int tid = threadIdx.x;

    float v[4];
    float s = 0.f, s2 = 0.f;
#pragma unroll
    for (int i = 0; i < 4; i++) {
        v[i] = xr[tid + i * 256];
        s  += v[i];
        s2 += v[i] * v[i];
    }
#pragma unroll
    for (int o = 16; o > 0; o >>= 1) {
        s  += __shfl_xor_sync(0xffffffffu, s,  o);
        s2 += __shfl_xor_sync(0xffffffffu, s2, o);
    }
    __shared__ float sh[2][8];
    int w = tid >> 5, l = tid & 31;
    if (l == 0) { sh[0][w] = s; sh[1][w] = s2; }
    __syncthreads();
    float ts = 0.f, ts2 = 0.f;
#pragma unroll
    for (int i = 0; i < 8; i++) { ts += sh[0][i]; ts2 += sh[1][i]; }
    float mean = ts * (1.0f / D);
    float var  = ts2 * (1.0f / D) - mean * mean;
    float inv  = rsqrtf(var + 1e-5f);
#pragma unroll
    for (int i = 0; i < 4; i++) {
        int idx = tid + i * 256;
        orow[idx] = (v[i] - mean) * inv * gam[idx] + bet[idx];
    }
}

// ---------------- SGEMM: C = act(A@B + bias) + res ----------------
// 128x128 tile, BK=8, 256 threads, 8x8 per-thread register blocking.
// M,N multiples of 128; K multiple of 8 (true for all calls here).
__global__ void __launch_bounds__(256) gemm_kernel(
    const float* __restrict__ A, const float* __restrict__ Bm,
    const float* __restrict__ bias, const float* __restrict__ res,
    float* __restrict__ C, int M, int N, int K, int gelu_flag)
{
    __shared__ float As[8][128];
    __shared__ float Bs[8][128];

    int tid = threadIdx.x;
    int bn = blockIdx.x, bm = blockIdx.y;

    const float* Ab = A + (size_t)(bm * 128) * K;
    const float* Bb = Bm + bn * 128;

    int aRow = tid >> 1,  aCol = (tid & 1) * 4;
    int bRow = tid >> 5,  bCol = (tid & 31) * 4;
    int tx = tid & 15, ty = tid >> 4;

    float acc[8][8];
#pragma unroll
    for (int i = 0; i < 8; i++)
#pragma unroll
        for (int j = 0; j < 8; j++) acc[i][j] = 0.f;

    for (int k0 = 0; k0 < K; k0 += 8) {
        float4 a = *(const float4*)(Ab + (size_t)aRow * K + k0 + aCol);
        As[aCol + 0][aRow] = a.x;
        As[aCol + 1][aRow] = a.y;
        As[aCol + 2][aRow] = a.z;
        As[aCol + 3][aRow] = a.w;
        *(float4*)&Bs[bRow][bCol] = *(const float4*)(Bb + (size_t)(k0 + bRow) * N + bCol);
        __syncthreads();
#pragma unroll
        for (int kk = 0; kk < 8; kk++) {
            float ar[8], br[8];
            *(float4*)(ar)     = *(float4*)&As[kk][ty * 8];
            *(float4*)(ar + 4) = *(float4*)&As[kk][ty * 8 + 4];
            *(float4*)(br)     = *(float4*)&Bs[kk][tx * 8];
            *(float4*)(br + 4) = *(float4*)&Bs[kk][tx * 8 + 4];
#pragma unroll
            for (int i = 0; i < 8; i++)
#pragma unroll
                for (int j = 0; j < 8; j++)
                    acc[i][j] += ar[i] * br[j];
        }
        __syncthreads();
    }

#pragma unroll
    for (int i = 0; i < 8; i++) {
        size_t row = (size_t)bm * 128 + ty * 8 + i;
        float* crow = C + row * N + bn * 128 + tx * 8;
        const float* rrow = res ? (res + row * N + bn * 128 + tx * 8) : nullptr;
#pragma unroll
        for (int j = 0; j < 8; j++) {
            float vv = acc[i][j];
            if (bias) vv += bias[bn * 128 + tx * 8 + j];
            if (gelu_flag) vv = 0.5f * vv * (1.0f + erff(vv * 0.70710678118654752f));
            if (rrow) vv += rrow[j];
            crow[j] = vv;
        }
    }
}

// ---------------- Attention (Longformer sparse, causal) ----------------
// Layout of Q/K/V/O: [B,T,D] with column h*64+d (no transpose needed).
// Warp per query; keys = {0} U [i-128, i]. Row T-1 handled by attn_last_kernel.
__global__ void __launch_bounds__(128) attn_kernel(
    const float* __restrict__ Q, const float* __restrict__ K,
    const float* __restrict__ V, float* __restrict__ O)
{
    int lane = threadIdx.x & 31;
    int warp = threadIdx.x >> 5;
    int i = blockIdx.x * 4 + warp;
    int h = blockIdx.y, b = blockIdx.z;
    if (i == T - 1) return;  // dense global row handled separately

    size_t base = (size_t)b * T * D + h * HD;
    const float* qp = Q + base + (size_t)i * D;
    float q0 = qp[lane] * 0.125f, q1 = qp[lane + 32] * 0.125f;

    float m = -1e30f, l = 0.f, o0 = 0.f, o1 = 0.f;
    int j0 = i - 128; if (j0 < 0) j0 = 0;

    int j = (j0 > 0) ? 0 : j0;           // process global key 0 first if outside window
    bool did_global = (j0 > 0);
    for (;;) {
        const float* kp = K + base + (size_t)j * D;
        float s = q0 * kp[lane] + q1 * kp[lane + 32];
#pragma unroll
        for (int o = 16; o > 0; o >>= 1) s += __shfl_xor_sync(0xffffffffu, s, o);
        float nm = fmaxf(m, s);
        float sc = __expf(m - nm);
        float p  = __expf(s - nm);
        const float* vp = V + base + (size_t)j * D;
        l  = l  * sc + p;
        o0 = o0 * sc + p * vp[lane];
        o1 = o1 * sc + p * vp[lane + 32];
        m = nm;
        if (did_global) { did_global = false; j = j0; continue; }
        if (++j > i) break;
    }
    float inv = 1.f / l;
    float* op = O + base + (size_t)i * D;
    op[lane]      = o0 * inv;
    op[lane + 32] = o1 * inv;
}

// Dense row i = T-1: 8 warps partition keys, log-sum-exp merge.
__global__ void __launch_bounds__(256) attn_last_kernel(
    const float* __restrict__ Q, const float* __restrict__ K,
    const float* __restrict__ V, float* __restrict__ O)
{
    int lane = threadIdx.x & 31;
    int warp = threadIdx.x >> 5;
    int h = blockIdx.x, b = blockIdx.y;
    const int i = T - 1;

    size_t base = (size_t)b * T * D + h * HD;
    const float* qp = Q + base + (size_t)i * D;
    float q0 = qp[lane] * 0.125f, q1 = qp[lane + 32] * 0.125f;

    float m = -1e30f, l = 0.f, o0 = 0.f, o1 = 0.f;
    for (int j = warp; j < T; j += 8) {
        const float* kp = K + base + (size_t)j * D;
        float s = q0 * kp[lane] + q1 * kp[lane + 32];
#pragma unroll
        for (int o = 16; o > 0; o >>= 1) s += __shfl_xor_sync(0xffffffffu, s, o);
        float nm = fmaxf(m, s);
        float sc = __expf(m - nm);
        float p  = __expf(s - nm);
        const float* vp = V + base + (size_t)j * D;
        l  = l  * sc + p;
        o0 = o0 * sc + p * vp[lane];
        o1 = o1 * sc + p * vp[lane + 32];
        m = nm;
    }
    __shared__ float sm[8], sl[8], so[8][64];
    if (lane == 0) { sm[warp] = m; sl[warp] = l; }
    so[warp][lane] = o0; so[warp][lane + 32] = o1;
    __syncthreads();
    if (warp == 0) {
        float gm = -1e30f;
#pragma unroll
        for (int w = 0; w < 8; w++) gm = fmaxf(gm, sm[w]);
        float gl = 0.f, a0 = 0.f, a1 = 0.f;
#pragma unroll
        for (int w = 0; w < 8; w++) {
            float sc = __expf(sm[w] - gm);
            gl += sc * sl[w];
            a0 += sc * so[w][lane];
            a1 += sc * so[w][lane + 32];
        }
        float inv = 1.f / gl;
        float* op = O + base + (size_t)i * D;
        op[lane]      = a0 * inv;
        op[lane + 32] = a1 * inv;
    }
}

// ---------------- launch ----------------
extern "C" void kernel_launch(void* const* d_in, const int* in_sizes, int n_in,
                              void* d_out, int out_size)
{
    const float* x    = (const float*)d_in[0];
    const float* ln1g = (const float*)d_in[1];
    const float* ln1b = (const float*)d_in[2];
    const float* ln2g = (const float*)d_in[3];
    const float* ln2b = (const float*)d_in[4];
    const float* Wq   = (const float*)d_in[5];
    const float* Wk   = (const float*)d_in[6];
    const float* Wv   = (const float*)d_in[7];
    const float* Wo   = (const float*)d_in[8];
    const float* bo   = (const float*)d_in[9];
    const float* W1   = (const float*)d_in[10];
    const float* b1   = (const float*)d_in[11];
    const float* W2   = (const float*)d_in[12];
    const float* b2   = (const float*)d_in[13];
    float* out = (float*)d_out;

    float *h, *q, *k, *v, *att, *x2, *h2, *f1;
    cudaGetSymbolAddress((void**)&h,   g_h);
    cudaGetSymbolAddress((void**)&q,   g_q);
    cudaGetSymbolAddress((void**)&k,   g_k);
    cudaGetSymbolAddress((void**)&v,   g_v);
    cudaGetSymbolAddress((void**)&att, g_att);
    cudaGetSymbolAddress((void**)&x2,  g_x2);
    cudaGetSymbolAddress((void**)&h2,  g_h2);
    cudaGetSymbolAddress((void**)&f1,  g_f1);

    // 1. h = LN1(x)
    ln_kernel<<<NT, 256>>>(x, ln1g, ln1b, h);

    // 2. Q,K,V = h @ W{q,k,v}
    dim3 gD(D / 128, NT / 128);
    gemm_kernel<<<gD, 256>>>(h, Wq, nullptr, nullptr, q, NT, D, D, 0);
    gemm_kernel<<<gD, 256>>>(h, Wk, nullptr, nullptr, k, NT, D, D, 0);
    gemm_kernel<<<gD, 256>>>(h, Wv, nullptr, nullptr, v, NT, D, D, 0);

    // 3. sparse attention
    attn_kernel<<<dim3(T / 4, NH, Bsz), 128>>>(q, k, v, att);
    attn_last_kernel<<<dim3(NH, Bsz), 256>>>(q, k, v, att);

    // 4. x2 = x + att @ Wo + bo
    gemm_kernel<<<gD, 256>>>(att, Wo, bo, x, x2, NT, D, D, 0);

    // 5. h2 = LN2(x2)
    ln_kernel<<<NT, 256>>>(x2, ln2g, ln2b, h2);

    // 6. f1 = gelu(h2 @ W1 + b1)
    dim3 gF(DFF / 128, NT / 128);
    gemm_kernel<<<gF, 256>>>(h2, W1, b1, nullptr, f1, NT, DFF, D, 1);

    // 7. out = x2 + f1 @ W2 + b2
    gemm_kernel<<<gD, 256>>>(f1, W2, b2, x2, out, NT, D, DFF, 0);
}

// round 6
// speedup vs baseline: 1.7904x; 1.7904x over previous
#include <cuda_runtime.h>
#include <cuda_bf16.h>
#include <math.h>
#include <stdint.h>

#define Bsz 2
#define T 2048
#define D 1024
#define NH 16
#define HD 64
#define NT (Bsz*T)    /* 4096 rows */
#define DFF 4096

typedef __nv_bfloat16 bf16;

// ---------------- scratch (device globals; no allocation allowed) ----------------
__device__ float g_q [NT*D];
__device__ float g_k [NT*D];
__device__ float g_v [NT*D];
__device__ float g_x2[NT*D];

__device__ bf16 g_hh [NT*D],  g_hl [NT*D];          // LN1 out pair
__device__ bf16 g_ah [NT*D],  g_al [NT*D];          // attention out pair
__device__ bf16 g_h2h[NT*D],  g_h2l[NT*D];          // LN2 out pair
__device__ bf16 g_f1h[(size_t)NT*DFF], g_f1l[(size_t)NT*DFF];   // FFN mid pair

__device__ bf16 g_WqTh[D*D], g_WqTl[D*D];
__device__ bf16 g_WkTh[D*D], g_WkTl[D*D];
__device__ bf16 g_WvTh[D*D], g_WvTl[D*D];
__device__ bf16 g_WoTh[D*D], g_WoTl[D*D];
__device__ bf16 g_W1Th[(size_t)D*DFF], g_W1Tl[(size_t)D*DFF];   // [DFF, D]
__device__ bf16 g_W2Th[(size_t)D*DFF], g_W2Tl[(size_t)D*DFF];   // [D, DFF]

// ---------------- helpers ----------------
__device__ __forceinline__ uint32_t s2u(const void* p) {
    uint32_t a;
    asm("{ .reg .u64 t; cvta.to.shared.u64 t, %1; cvt.u32.u64 %0, t; }" : "=r"(a) : "l"(p));
    return a;
}
__device__ __forceinline__ void cp16(uint32_t d, const void* s) {
    asm volatile("cp.async.cg.shared.global [%0], [%1], 16;" :: "r"(d), "l"(s));
}
__device__ __forceinline__ void ldm4(uint32_t* r, uint32_t addr) {
    asm volatile("ldmatrix.sync.aligned.m8n8.x4.shared.b16 {%0,%1,%2,%3}, [%4];"
        : "=r"(r[0]), "=r"(r[1]), "=r"(r[2]), "=r"(r[3]) : "r"(addr));
}
__device__ __forceinline__ void mma_bf16(float* d, const uint32_t* a, const uint32_t* b) {
    asm volatile("mma.sync.aligned.m16n8k16.row.col.f32.bf16.bf16.f32 "
        "{%0,%1,%2,%3}, {%4,%5,%6,%7}, {%8,%9}, {%0,%1,%2,%3};"
        : "+f"(d[0]), "+f"(d[1]), "+f"(d[2]), "+f"(d[3])
        : "r"(a[0]), "r"(a[1]), "r"(a[2]), "r"(a[3]), "r"(b[0]), "r"(b[1]));
}
__device__ __forceinline__ void split2(float v, bf16* hi, bf16* lo) {
    bf16 h = __float2bfloat16(v);
    *hi = h;
    *lo = __float2bfloat16(v - __bfloat162float(h));
}

// ---------------- LayerNorm: one block per row, writes bf16 hi/lo pair ----------------
__global__ void __launch_bounds__(256) ln_kernel(const float* __restrict__ x,
                                                 const float* __restrict__ gam,
                                                 const float* __restrict__ bet,
                                                 bf16* __restrict__ oh,
                                                 bf16* __restrict__ ol)
{
    int row = blockIdx.x;
    const float* xr = x + (size_t)row * D;
    int tid = threadIdx.x;

    float v[4];
    float s = 0.f, s2 = 0.f;
#pragma unroll
    for (int i = 0; i < 4; i++) {
        v[i] = xr[tid + i * 256];
        s  += v[i];
        s2 += v[i] * v[i];
    }
#pragma unroll
    for (int o = 16; o > 0; o >>= 1) {
        s  += __shfl_xor_sync(0xffffffffu, s,  o);
        s2 += __shfl_xor_sync(0xffffffffu, s2, o);
    }
    __shared__ float sh[2][8];
    int w = tid >> 5, l = tid & 31;
    if (l == 0) { sh[0][w] = s; sh[1][w] = s2; }
    __syncthreads();
    float ts = 0.f, ts2 = 0.f;
#pragma unroll
    for (int i = 0; i < 8; i++) { ts += sh[0][i]; ts2 += sh[1][i]; }
    float mean = ts * (1.0f / D);
    float var  = ts2 * (1.0f / D) - mean * mean;
    float inv  = rsqrtf(var + 1e-5f);
#pragma unroll
    for (int i = 0; i < 4; i++) {
        int idx = tid + i * 256;
        float vv = (v[i] - mean) * inv * gam[idx] + bet[idx];
        size_t o = (size_t)row * D + idx;
        bf16 hi, lo; split2(vv, &hi, &lo);
        oh[o] = hi; ol[o] = lo;
    }
}

// ---------------- transpose + split: W[K,N] fp32 -> Th/Tl [N,K] bf16 ----------------
__global__ void __launch_bounds__(256) tsplit_kernel(const float* __restrict__ W,
                                                     bf16* __restrict__ Th,
                                                     bf16* __restrict__ Tl,
                                                     int K, int N)
{
    __shared__ float t[32][33];
    int n0 = blockIdx.x * 32, k0 = blockIdx.y * 32;
    int tx = threadIdx.x, ty = threadIdx.y;   // (32, 8)
#pragma unroll
    for (int j = 0; j < 4; j++)
        t[ty + j * 8][tx] = W[(size_t)(k0 + ty + j * 8) * N + n0 + tx];
    __syncthreads();
#pragma unroll
    for (int j = 0; j < 4; j++) {
        float v = t[tx][ty + j * 8];
        size_t o = (size_t)(n0 + ty + j * 8) * K + k0 + tx;
        bf16 hi, lo; split2(v, &hi, &lo);
        Th[o] = hi; Tl[o] = lo;
    }
}

// ---------------- bf16x3 HMMA GEMM: C = act(A@B^T + bias) + res ----------------
// A pair [M,K] row-major bf16; B pair [N,K] row-major bf16 (pre-transposed).
// CTA tile 128x128, BK=32, 8 warps (64x32 warp tile), double-buffered cp.async.
// Per warp, per k16 step: 3 passes (Ah*Bh, Ah*Bl, Al*Bh) into the same fp32 acc.
// smem per stage: 4 arrays [128 rows][40 bf16] (80B padded rows) = 40960 B.
#define MM_SMEM (2 * 40960)

__global__ void __launch_bounds__(256, 1) mm_kernel(
    const bf16* __restrict__ Ah, const bf16* __restrict__ Al,
    const bf16* __restrict__ Bh, const bf16* __restrict__ Bl,
    const float* __restrict__ bias, const float* __restrict__ res,
    float* __restrict__ Cf, bf16* __restrict__ Ch, bf16* __restrict__ Cl,
    int K, int N, int gelu_flag)
{
    extern __shared__ char smem[];
    uint32_t sb = s2u(smem);
    int tid = threadIdx.x, warp = tid >> 5, lane = tid & 31;
    int bn = blockIdx.x, bm = blockIdx.y;
    int wm = warp & 1, wn = warp >> 1;     // warp tile: rows wm*64, cols wn*32

    const int nchunk = K / 32;

    // global load base: 2 chunks (32B) per thread per array
    int r0 = tid >> 1;                 // row 0..127
    int cp0 = (tid & 1) * 2;           // 16B-chunk pair 0 or 2
    const char* pAh = (const char*)Ah + ((size_t)(bm * 128 + r0) * K) * 2 + cp0 * 16;
    const char* pAl = (const char*)Al + ((size_t)(bm * 128 + r0) * K) * 2 + cp0 * 16;
    const char* pBh = (const char*)Bh + ((size_t)(bn * 128 + r0) * K) * 2 + cp0 * 16;
    const char* pBl = (const char*)Bl + ((size_t)(bn * 128 + r0) * K) * 2 + cp0 * 16;
    uint32_t so = r0 * 80 + cp0 * 16;

    auto load_stage = [&](int st, int c) {
        uint32_t base = sb + st * 40960 + so;
        size_t g = (size_t)c * 64;     // 32 bf16 = 64 bytes
        cp16(base +     0, pAh + g); cp16(base +     16, pAh + g + 16);
        cp16(base + 10240, pAl + g); cp16(base + 10240 + 16, pAl + g + 16);
        cp16(base + 20480, pBh + g); cp16(base + 20480 + 16, pBh + g + 16);
        cp16(base + 30720, pBl + g); cp16(base + 30720 + 16, pBl + g + 16);
    };

    float acc[4][4][4];
#pragma unroll
    for (int i = 0; i < 4; i++)
#pragma unroll
        for (int j = 0; j < 4; j++)
#pragma unroll
            for (int r = 0; r < 4; r++) acc[i][j][r] = 0.f;

    load_stage(0, 0);
    asm volatile("cp.async.commit_group;" ::: "memory");

    // ldmatrix lane addressing (byte offsets within a stage)
    int a_row = wm * 64 + (lane & 15);
    int a_kb  = (lane >> 4) * 16;                       // 16B k-subblock
    int b_row = wn * 32 + (lane & 7) + ((lane >> 4) << 3);
    int b_kb  = ((lane >> 3) & 1) * 16;

    for (int it = 0; it < nchunk; it++) {
        if (it + 1 < nchunk) {
            load_stage((it + 1) & 1, it + 1);
            asm volatile("cp.async.commit_group;" ::: "memory");
            asm volatile("cp.async.wait_group 1;" ::: "memory");
        } else {
            asm volatile("cp.async.wait_group 0;" ::: "memory");
        }
        __syncthreads();

        uint32_t stb = sb + (it & 1) * 40960;
#pragma unroll
        for (int ks = 0; ks < 2; ks++) {
            uint32_t aH[4][4], aL[4][4], bH[4][2], bL[4][2];
#pragma unroll
            for (int mt = 0; mt < 4; mt++) {
                uint32_t ad = stb + (a_row + mt * 16) * 80 + ks * 32 + a_kb;
                ldm4(aH[mt], ad);
                ldm4(aL[mt], ad + 10240);
            }
#pragma unroll
            for (int np = 0; np < 2; np++) {
                uint32_t bd = stb + 20480 + (b_row + np * 16) * 80 + ks * 32 + b_kb;
                uint32_t r[4];
                ldm4(r, bd);
                bH[np * 2][0] = r[0]; bH[np * 2][1] = r[1];
                bH[np * 2 + 1][0] = r[2]; bH[np * 2 + 1][1] = r[3];
                ldm4(r, bd + 10240);
                bL[np * 2][0] = r[0]; bL[np * 2][1] = r[1];
                bL[np * 2 + 1][0] = r[2]; bL[np * 2 + 1][1] = r[3];
            }
#pragma unroll
            for (int mt = 0; mt < 4; mt++)
#pragma unroll
                for (int nt = 0; nt < 4; nt++) {
                    mma_bf16(acc[mt][nt], aH[mt], bH[nt]);
                    mma_bf16(acc[mt][nt], aH[mt], bL[nt]);
                    mma_bf16(acc[mt][nt], aL[mt], bH[nt]);
                }
        }
        __syncthreads();
    }

    // ---- epilogue: registers -> global, fused bias/gelu/res/split ----
    int qr = lane >> 2, qc = (lane & 3) * 2;
#pragma unroll
    for (int mt = 0; mt < 4; mt++) {
#pragma unroll
        for (int nt = 0; nt < 4; nt++) {
            int col = bn * 128 + wn * 32 + nt * 8 + qc;
            float b0 = bias ? bias[col] : 0.f;
            float b1 = bias ? bias[col + 1] : 0.f;
#pragma unroll
            for (int half = 0; half < 2; half++) {
                size_t row = (size_t)bm * 128 + wm * 64 + mt * 16 + qr + half * 8;
                float v0 = acc[mt][nt][half * 2]     + b0;
                float v1 = acc[mt][nt][half * 2 + 1] + b1;
                if (gelu_flag) {
                    v0 = 0.5f * v0 * (1.0f + erff(v0 * 0.70710678118654752f));
                    v1 = 0.5f * v1 * (1.0f + erff(v1 * 0.70710678118654752f));
                }
                size_t idx = row * (size_t)N + col;
                if (res) { v0 += res[idx]; v1 += res[idx + 1]; }
                if (Cf) {
                    *(float2*)(Cf + idx) = make_float2(v0, v1);
                } else {
                    bf16 h0, l0, h1, l1;
                    split2(v0, &h0, &l0); split2(v1, &h1, &l1);
                    *(__nv_bfloat162*)(Ch + idx) = __nv_bfloat162(h0, h1);
                    *(__nv_bfloat162*)(Cl + idx) = __nv_bfloat162(l0, l1);
                }
            }
        }
    }
}

// ---------------- Attention (Longformer sparse, causal) — outputs bf16 pair ----------------
__global__ void __launch_bounds__(128) attn_kernel(
    const float* __restrict__ Q, const float* __restrict__ K,
    const float* __restrict__ V, bf16* __restrict__ Oh, bf16* __restrict__ Ol)
{
    int lane = threadIdx.x & 31;
    int warp = threadIdx.x >> 5;
    int i = blockIdx.x * 4 + warp;
    int h = blockIdx.y, b = blockIdx.z;
    if (i == T - 1) return;

    size_t base = (size_t)b * T * D + h * HD;
    const float* qp = Q + base + (size_t)i * D;
    float q0 = qp[lane] * 0.125f, q1 = qp[lane + 32] * 0.125f;

    float m = -1e30f, l = 0.f, o0 = 0.f, o1 = 0.f;
    int j0 = i - 128; if (j0 < 0) j0 = 0;

    int j = (j0 > 0) ? 0 : j0;
    bool did_global = (j0 > 0);
    for (;;) {
        const float* kp = K + base + (size_t)j * D;
        float s = q0 * kp[lane] + q1 * kp[lane + 32];
#pragma unroll
        for (int o = 16; o > 0; o >>= 1) s += __shfl_xor_sync(0xffffffffu, s, o);
        float nm = fmaxf(m, s);
        float sc = __expf(m - nm);
        float p  = __expf(s - nm);
        const float* vp = V + base + (size_t)j * D;
        l  = l  * sc + p;
        o0 = o0 * sc + p * vp[lane];
        o1 = o1 * sc + p * vp[lane + 32];
        m = nm;
        if (did_global) { did_global = false; j = j0; continue; }
        if (++j > i) break;
    }
    float inv = 1.f / l;
    size_t oidx = base + (size_t)i * D;
    float v0 = o0 * inv, v1 = o1 * inv;
    bf16 hi, lo;
    split2(v0, &hi, &lo); Oh[oidx + lane] = hi;      Ol[oidx + lane] = lo;
    split2(v1, &hi, &lo); Oh[oidx + lane + 32] = hi; Ol[oidx + lane + 32] = lo;
}

__global__ void __launch_bounds__(256) attn_last_kernel(
    const float* __restrict__ Q, const float* __restrict__ K,
    const float* __restrict__ V, bf16* __restrict__ Oh, bf16* __restrict__ Ol)
{
    int lane = threadIdx.x & 31;
    int warp = threadIdx.x >> 5;
    int h = blockIdx.x, b = blockIdx.y;
    const int i = T - 1;

    size_t base = (size_t)b * T * D + h * HD;
    const float* qp = Q + base + (size_t)i * D;
    float q0 = qp[lane] * 0.125f, q1 = qp[lane + 32] * 0.125f;

    float m = -1e30f, l = 0.f, o0 = 0.f, o1 = 0.f;
    for (int j = warp; j < T; j += 8) {
        const float* kp = K + base + (size_t)j * D;
        float s = q0 * kp[lane] + q1 * kp[lane + 32];
#pragma unroll
        for (int o = 16; o > 0; o >>= 1) s += __shfl_xor_sync(0xffffffffu, s, o);
        float nm = fmaxf(m, s);
        float sc = __expf(m - nm);
        float p  = __expf(s - nm);
        const float* vp = V + base + (size_t)j * D;
        l  = l  * sc + p;
        o0 = o0 * sc + p * vp[lane];
        o1 = o1 * sc + p * vp[lane + 32];
        m = nm;
    }
    __shared__ float sm[8], sl[8], so[8][64];
    if (lane == 0) { sm[warp] = m; sl[warp] = l; }
    so[warp][lane] = o0; so[warp][lane + 32] = o1;
    __syncthreads();
    if (warp == 0) {
        float gm = -1e30f;
#pragma unroll
        for (int w = 0; w < 8; w++) gm = fmaxf(gm, sm[w]);
        float gl = 0.f, a0 = 0.f, a1 = 0.f;
#pragma unroll
        for (int w = 0; w < 8; w++) {
            float sc = __expf(sm[w] - gm);
            gl += sc * sl[w];
            a0 += sc * so[w][lane];
            a1 += sc * so[w][lane + 32];
        }
        float inv = 1.f / gl;
        size_t oidx = base + (size_t)i * D;
        float v0 = a0 * inv, v1 = a1 * inv;
        bf16 hi, lo;
        split2(v0, &hi, &lo); Oh[oidx + lane] = hi;      Ol[oidx + lane] = lo;
        split2(v1, &hi, &lo); Oh[oidx + lane + 32] = hi; Ol[oidx + lane + 32] = lo;
    }
}

// ---------------- launch ----------------
extern "C" void kernel_launch(void* const* d_in, const int* in_sizes, int n_in,
                              void* d_out, int out_size)
{
    const float* x    = (const float*)d_in[0];
    const float* ln1g = (const float*)d_in[1];
    const float* ln1b = (const float*)d_in[2];
    const float* ln2g = (const float*)d_in[3];
    const float* ln2b = (const float*)d_in[4];
    const float* Wq   = (const float*)d_in[5];
    const float* Wk   = (const float*)d_in[6];
    const float* Wv   = (const float*)d_in[7];
    const float* Wo   = (const float*)d_in[8];
    const float* bo   = (const float*)d_in[9];
    const float* W1   = (const float*)d_in[10];
    const float* b1   = (const float*)d_in[11];
    const float* W2   = (const float*)d_in[12];
    const float* b2   = (const float*)d_in[13];
    float* out = (float*)d_out;

    cudaFuncSetAttribute(mm_kernel, cudaFuncAttributeMaxDynamicSharedMemorySize, MM_SMEM);

    float *q, *k, *v, *x2;
    bf16 *hh, *hl, *ah, *al, *h2h, *h2l, *f1h, *f1l;
    bf16 *WqTh, *WqTl, *WkTh, *WkTl, *WvTh, *WvTl, *WoTh, *WoTl, *W1Th, *W1Tl, *W2Th, *W2Tl;
    cudaGetSymbolAddress((void**)&q,   g_q);
    cudaGetSymbolAddress((void**)&k,   g_k);
    cudaGetSymbolAddress((void**)&v,   g_v);
    cudaGetSymbolAddress((void**)&x2,  g_x2);
    cudaGetSymbolAddress((void**)&hh,  g_hh);  cudaGetSymbolAddress((void**)&hl,  g_hl);
    cudaGetSymbolAddress((void**)&ah,  g_ah);  cudaGetSymbolAddress((void**)&al,  g_al);
    cudaGetSymbolAddress((void**)&h2h, g_h2h); cudaGetSymbolAddress((void**)&h2l, g_h2l);
    cudaGetSymbolAddress((void**)&f1h, g_f1h); cudaGetSymbolAddress((void**)&f1l, g_f1l);
    cudaGetSymbolAddress((void**)&WqTh, g_WqTh); cudaGetSymbolAddress((void**)&WqTl, g_WqTl);
    cudaGetSymbolAddress((void**)&WkTh, g_WkTh); cudaGetSymbolAddress((void**)&WkTl, g_WkTl);
    cudaGetSymbolAddress((void**)&WvTh, g_WvTh); cudaGetSymbolAddress((void**)&WvTl, g_WvTl);
    cudaGetSymbolAddress((void**)&WoTh, g_WoTh); cudaGetSymbolAddress((void**)&WoTl, g_WoTl);
    cudaGetSymbolAddress((void**)&W1Th, g_W1Th); cudaGetSymbolAddress((void**)&W1Tl, g_W1Tl);
    cudaGetSymbolAddress((void**)&W2Th, g_W2Th); cudaGetSymbolAddress((void**)&W2Tl, g_W2Tl);

    dim3 tb(32, 8);
    // weight transpose+split: W[K,N] -> [N,K] bf16 pair
    tsplit_kernel<<<dim3(D / 32, D / 32), tb>>>(Wq, WqTh, WqTl, D, D);
    tsplit_kernel<<<dim3(D / 32, D / 32), tb>>>(Wk, WkTh, WkTl, D, D);
    tsplit_kernel<<<dim3(D / 32, D / 32), tb>>>(Wv, WvTh, WvTl, D, D);
    tsplit_kernel<<<dim3(D / 32, D / 32), tb>>>(Wo, WoTh, WoTl, D, D);
    tsplit_kernel<<<dim3(DFF / 32, D / 32), tb>>>(W1, W1Th, W1Tl, D, DFF);
    tsplit_kernel<<<dim3(D / 32, DFF / 32), tb>>>(W2, W2Th, W2Tl, DFF, D);

    // 1. h = LN1(x)  (bf16 pair)
    ln_kernel<<<NT, 256>>>(x, ln1g, ln1b, hh, hl);

    // 2. Q,K,V = h @ W{q,k,v}   (fp32 out for attention)
    dim3 gD(D / 128, NT / 128);
    mm_kernel<<<gD, 256, MM_SMEM>>>(hh, hl, WqTh, WqTl, nullptr, nullptr, q, nullptr, nullptr, D, D, 0);
    mm_kernel<<<gD, 256, MM_SMEM>>>(hh, hl, WkTh, WkTl, nullptr, nullptr, k, nullptr, nullptr, D, D, 0);
    mm_kernel<<<gD, 256, MM_SMEM>>>(hh, hl, WvTh, WvTl, nullptr, nullptr, v, nullptr, nullptr, D, D, 0);

    // 3. sparse attention (bf16 pair out)
    attn_kernel<<<dim3(T / 4, NH, Bsz), 128>>>(q, k, v, ah, al);
    attn_last_kernel<<<dim3(NH, Bsz), 256>>>(q, k, v, ah, al);

    // 4. x2 = x + att @ Wo + bo   (fp32)
    mm_kernel<<<gD, 256, MM_SMEM>>>(ah, al, WoTh, WoTl, bo, x, x2, nullptr, nullptr, D, D, 0);

    // 5. h2 = LN2(x2) (bf16 pair)
    ln_kernel<<<NT, 256>>>(x2, ln2g, ln2b, h2h, h2l);

    // 6. f1 = gelu(h2 @ W1 + b1)  (bf16 pair out)
    dim3 gF(DFF / 128, NT / 128);
    mm_kernel<<<gF, 256, MM_SMEM>>>(h2h, h2l, W1Th, W1Tl, b1, nullptr, nullptr, f1h, f1l, D, DFF, 1);

    // 7. out = x2 + f1 @ W2 + b2  (fp32)
    mm_kernel<<<gD, 256, MM_SMEM>>>(f1h, f1l, W2Th, W2Tl, b2, x2, out, nullptr, nullptr, DFF, D, 0);
}

// round 7
// speedup vs baseline: 2.0031x; 1.1188x over previous
#include <cuda_runtime.h>
#include <cuda_bf16.h>
#include <math.h>
#include <stdint.h>

#define Bsz 2
#define T 2048
#define D 1024
#define NH 16
#define HD 64
#define NT (Bsz*T)    /* 4096 rows */
#define DFF 4096

typedef __nv_bfloat16 bf16;

// ---------------- scratch ----------------
__device__ float g_q [NT*D];
__device__ float g_k [NT*D];
__device__ float g_v [NT*D];
__device__ float g_x2[NT*D];

__device__ bf16 g_hh [NT*D],  g_hl [NT*D];
__device__ bf16 g_ah [NT*D],  g_al [NT*D];
__device__ bf16 g_h2h[NT*D],  g_h2l[NT*D];
__device__ bf16 g_f1h[(size_t)NT*DFF], g_f1l[(size_t)NT*DFF];

__device__ bf16 g_WqTh[D*D], g_WqTl[D*D];
__device__ bf16 g_WkTh[D*D], g_WkTl[D*D];
__device__ bf16 g_WvTh[D*D], g_WvTl[D*D];
__device__ bf16 g_WoTh[D*D], g_WoTl[D*D];
__device__ bf16 g_W1Th[(size_t)D*DFF], g_W1Tl[(size_t)D*DFF];
__device__ bf16 g_W2Th[(size_t)D*DFF], g_W2Tl[(size_t)D*DFF];

// ---------------- helpers ----------------
__device__ __forceinline__ uint32_t s2u(const void* p) {
    uint32_t a;
    asm("{ .reg .u64 t; cvta.to.shared.u64 t, %1; cvt.u32.u64 %0, t; }" : "=r"(a) : "l"(p));
    return a;
}
__device__ __forceinline__ void cp16(uint32_t d, const void* s) {
    asm volatile("cp.async.cg.shared.global [%0], [%1], 16;" :: "r"(d), "l"(s));
}
__device__ __forceinline__ void ldm4(uint32_t* r, uint32_t addr) {
    asm volatile("ldmatrix.sync.aligned.m8n8.x4.shared.b16 {%0,%1,%2,%3}, [%4];"
        : "=r"(r[0]), "=r"(r[1]), "=r"(r[2]), "=r"(r[3]) : "r"(addr));
}
__device__ __forceinline__ void mma_bf16(float* d, const uint32_t* a, const uint32_t* b) {
    asm volatile("mma.sync.aligned.m16n8k16.row.col.f32.bf16.bf16.f32 "
        "{%0,%1,%2,%3}, {%4,%5,%6,%7}, {%8,%9}, {%0,%1,%2,%3};"
        : "+f"(d[0]), "+f"(d[1]), "+f"(d[2]), "+f"(d[3])
        : "r"(a[0]), "r"(a[1]), "r"(a[2]), "r"(a[3]), "r"(b[0]), "r"(b[1]));
}
__device__ __forceinline__ void split2(float v, bf16* hi, bf16* lo) {
    bf16 h = __float2bfloat16(v);
    *hi = h;
    *lo = __float2bfloat16(v - __bfloat162float(h));
}

// ---------------- LayerNorm ----------------
__global__ void __launch_bounds__(256) ln_kernel(const float* __restrict__ x,
                                                 const float* __restrict__ gam,
                                                 const float* __restrict__ bet,
                                                 bf16* __restrict__ oh,
                                                 bf16* __restrict__ ol)
{
    int row = blockIdx.x;
    const float* xr = x + (size_t)row * D;
    int tid = threadIdx.x;

    float v[4];
    float s = 0.f, s2 = 0.f;
#pragma unroll
    for (int i = 0; i < 4; i++) {
        v[i] = xr[tid + i * 256];
        s  += v[i];
        s2 += v[i] * v[i];
    }
#pragma unroll
    for (int o = 16; o > 0; o >>= 1) {
        s  += __shfl_xor_sync(0xffffffffu, s,  o);
        s2 += __shfl_xor_sync(0xffffffffu, s2, o);
    }
    __shared__ float sh[2][8];
    int w = tid >> 5, l = tid & 31;
    if (l == 0) { sh[0][w] = s; sh[1][w] = s2; }
    __syncthreads();
    float ts = 0.f, ts2 = 0.f;
#pragma unroll
    for (int i = 0; i < 8; i++) { ts += sh[0][i]; ts2 += sh[1][i]; }
    float mean = ts * (1.0f / D);
    float var  = ts2 * (1.0f / D) - mean * mean;
    float inv  = rsqrtf(var + 1e-5f);
#pragma unroll
    for (int i = 0; i < 4; i++) {
        int idx = tid + i * 256;
        float vv = (v[i] - mean) * inv * gam[idx] + bet[idx];
        size_t o = (size_t)row * D + idx;
        bf16 hi, lo; split2(vv, &hi, &lo);
        oh[o] = hi; ol[o] = lo;
    }
}

// ---------------- transpose + split ----------------
__global__ void __launch_bounds__(256) tsplit_kernel(const float* __restrict__ W,
                                                     bf16* __restrict__ Th,
                                                     bf16* __restrict__ Tl,
                                                     int K, int N)
{
    __shared__ float t[32][33];
    int n0 = blockIdx.x * 32, k0 = blockIdx.y * 32;
    int tx = threadIdx.x, ty = threadIdx.y;
#pragma unroll
    for (int j = 0; j < 4; j++)
        t[ty + j * 8][tx] = W[(size_t)(k0 + ty + j * 8) * N + n0 + tx];
    __syncthreads();
#pragma unroll
    for (int j = 0; j < 4; j++) {
        float v = t[tx][ty + j * 8];
        size_t o = (size_t)(n0 + ty + j * 8) * K + k0 + tx;
        bf16 hi, lo; split2(v, &hi, &lo);
        Th[o] = hi; Tl[o] = lo;
    }
}

// ---------------- bf16x3 HMMA GEMM core ----------------
// CTA tile 256x128, 8 warps, warp tile 64x64 (wm=warp&3, wn=warp>>2), BK=32.
// smem stage: A-hi[256x80B], A-lo, B-hi[128x80B], B-lo = 61440 B; double buffered.
#define STG 61440
#define MM_SMEM (2 * STG)

__device__ __forceinline__ void mm_body(
    const bf16* __restrict__ Ah, const bf16* __restrict__ Al,
    const bf16* __restrict__ Bh, const bf16* __restrict__ Bl,
    const float* __restrict__ bias, const float* __restrict__ res,
    float* __restrict__ Cf, bf16* __restrict__ Ch, bf16* __restrict__ Cl,
    int K, int N, int gelu_flag, int bm, int bnc, char* smem)
{
    uint32_t sb = s2u(smem);
    int tid = threadIdx.x, warp = tid >> 5, lane = tid & 31;
    int wm = warp & 3, wn = warp >> 2;
    const int nchunk = K / 32;

    int lr = tid >> 2;          // 0..63
    int cb = (tid & 3) * 16;    // byte chunk in a 64B k-slab

    auto load_stage = [&](int st, int c) {
        uint32_t base = sb + st * STG;
        size_t ko = (size_t)c * 64 + cb;
#pragma unroll
        for (int i = 0; i < 4; i++) {
            int r = lr + i * 64;
            size_t g = ((size_t)(bm * 256 + r) * K) * 2 + ko;
            uint32_t s = base + r * 80 + cb;
            cp16(s,         (const char*)Ah + g);
            cp16(s + 20480, (const char*)Al + g);
        }
#pragma unroll
        for (int i = 0; i < 2; i++) {
            int r = lr + i * 64;
            size_t g = ((size_t)(bnc * 128 + r) * K) * 2 + ko;
            uint32_t s = base + 40960 + r * 80 + cb;
            cp16(s,         (const char*)Bh + g);
            cp16(s + 10240, (const char*)Bl + g);
        }
    };

    float acc[4][8][4];
#pragma unroll
    for (int i = 0; i < 4; i++)
#pragma unroll
        for (int j = 0; j < 8; j++)
#pragma unroll
            for (int r = 0; r < 4; r++) acc[i][j][r] = 0.f;

    load_stage(0, 0);
    asm volatile("cp.async.commit_group;" ::: "memory");

    int a_row = wm * 64 + (lane & 15);
    int a_kb  = (lane >> 4) * 16;
    int b_row = wn * 64 + (lane & 7) + ((lane >> 4) << 3);
    int b_kb  = ((lane >> 3) & 1) * 16;

    for (int it = 0; it < nchunk; it++) {
        if (it + 1 < nchunk) {
            load_stage((it + 1) & 1, it + 1);
            asm volatile("cp.async.commit_group;" ::: "memory");
            asm volatile("cp.async.wait_group 1;" ::: "memory");
        } else {
            asm volatile("cp.async.wait_group 0;" ::: "memory");
        }
        __syncthreads();

        uint32_t stb = sb + (it & 1) * STG;
#pragma unroll
        for (int ks = 0; ks < 2; ks++) {
            uint32_t aH[4][4], aL[4][4];
#pragma unroll
            for (int mt = 0; mt < 4; mt++) {
                uint32_t ad = stb + (a_row + mt * 16) * 80 + ks * 32 + a_kb;
                ldm4(aH[mt], ad);
                ldm4(aL[mt], ad + 20480);
            }
#pragma unroll
            for (int np = 0; np < 4; np++) {
                uint32_t bh[4], bl[4];
                uint32_t bd = stb + 40960 + (b_row + np * 16) * 80 + ks * 32 + b_kb;
                ldm4(bh, bd);
                ldm4(bl, bd + 10240);
#pragma unroll
                for (int mt = 0; mt < 4; mt++) {
                    mma_bf16(acc[mt][np * 2],     aH[mt], bh);
                    mma_bf16(acc[mt][np * 2],     aH[mt], bl);
                    mma_bf16(acc[mt][np * 2],     aL[mt], bh);
                    mma_bf16(acc[mt][np * 2 + 1], aH[mt], bh + 2);
                    mma_bf16(acc[mt][np * 2 + 1], aH[mt], bl + 2);
                    mma_bf16(acc[mt][np * 2 + 1], aL[mt], bh + 2);
                }
            }
        }
        __syncthreads();
    }

    // ---- epilogue ----
    int qr = lane >> 2, qc = (lane & 3) * 2;
#pragma unroll
    for (int mt = 0; mt < 4; mt++) {
#pragma unroll
        for (int nt = 0; nt < 8; nt++) {
            int col = bnc * 128 + wn * 64 + nt * 8 + qc;
            float b0 = bias ? bias[col] : 0.f;
            float b1 = bias ? bias[col + 1] : 0.f;
#pragma unroll
            for (int half = 0; half < 2; half++) {
                size_t row = (size_t)bm * 256 + wm * 64 + mt * 16 + qr + half * 8;
                float v0 = acc[mt][nt][half * 2]     + b0;
                float v1 = acc[mt][nt][half * 2 + 1] + b1;
                if (gelu_flag) {
                    v0 = 0.5f * v0 * (1.0f + erff(v0 * 0.70710678118654752f));
                    v1 = 0.5f * v1 * (1.0f + erff(v1 * 0.70710678118654752f));
                }
                size_t idx = row * (size_t)N + col;
                if (res) { v0 += res[idx]; v1 += res[idx + 1]; }
                if (Cf) {
                    *(float2*)(Cf + idx) = make_float2(v0, v1);
                } else {
                    bf16 h0, l0, h1, l1;
                    split2(v0, &h0, &l0); split2(v1, &h1, &l1);
                    *(__nv_bfloat162*)(Ch + idx) = __nv_bfloat162(h0, h1);
                    *(__nv_bfloat162*)(Cl + idx) = __nv_bfloat162(l0, l1);
                }
            }
        }
    }
}

__global__ void __launch_bounds__(256, 1) mm_kernel(
    const bf16* __restrict__ Ah, const bf16* __restrict__ Al,
    const bf16* __restrict__ Bh, const bf16* __restrict__ Bl,
    const float* __restrict__ bias, const float* __restrict__ res,
    float* __restrict__ Cf, bf16* __restrict__ Ch, bf16* __restrict__ Cl,
    int K, int N, int gelu_flag)
{
    extern __shared__ char smem[];
    mm_body(Ah, Al, Bh, Bl, bias, res, Cf, Ch, Cl, K, N, gelu_flag,
            blockIdx.y, blockIdx.x, smem);
}

// Fused QKV: blockIdx.x in [0,24): sel = x>>3 picks {Wq,Wk,Wv} and {q,k,v}.
__global__ void __launch_bounds__(256, 1) qkv_kernel(
    const bf16* __restrict__ Ah, const bf16* __restrict__ Al,
    const bf16* __restrict__ Bqh, const bf16* __restrict__ Bql, float* __restrict__ Cq,
    const bf16* __restrict__ Bkh, const bf16* __restrict__ Bkl, float* __restrict__ Ck,
    const bf16* __restrict__ Bvh, const bf16* __restrict__ Bvl, float* __restrict__ Cv)
{
    extern __shared__ char smem[];
    int sel = blockIdx.x >> 3, bnc = blockIdx.x & 7;
    const bf16* Bh = (sel == 0) ? Bqh : (sel == 1) ? Bkh : Bvh;
    const bf16* Bl = (sel == 0) ? Bql : (sel == 1) ? Bkl : Bvl;
    float* Cf      = (sel == 0) ? Cq  : (sel == 1) ? Ck  : Cv;
    mm_body(Ah, Al, Bh, Bl, nullptr, nullptr, Cf, nullptr, nullptr, D, D, 0,
            blockIdx.y, bnc, smem);
}

// ---------------- Attention (Longformer sparse, causal) ----------------
__global__ void __launch_bounds__(128) attn_kernel(
    const float* __restrict__ Q, const float* __restrict__ K,
    const float* __restrict__ V, bf16* __restrict__ Oh, bf16* __restrict__ Ol)
{
    int lane = threadIdx.x & 31;
    int warp = threadIdx.x >> 5;
    int i = blockIdx.x * 4 + warp;
    int h = blockIdx.y, b = blockIdx.z;
    if (i == T - 1) return;

    size_t base = (size_t)b * T * D + h * HD;
    const float* qp = Q + base + (size_t)i * D;
    float q0 = qp[lane] * 0.125f, q1 = qp[lane + 32] * 0.125f;

    float m = -1e30f, l = 0.f, o0 = 0.f, o1 = 0.f;
    int j0 = i - 128; if (j0 < 0) j0 = 0;

    int j = (j0 > 0) ? 0 : j0;
    bool did_global = (j0 > 0);
    for (;;) {
        const float* kp = K + base + (size_t)j * D;
        float s = q0 * kp[lane] + q1 * kp[lane + 32];
#pragma unroll
        for (int o = 16; o > 0; o >>= 1) s += __shfl_xor_sync(0xffffffffu, s, o);
        float nm = fmaxf(m, s);
        float sc = __expf(m - nm);
        float p  = __expf(s - nm);
        const float* vp = V + base + (size_t)j * D;
        l  = l  * sc + p;
        o0 = o0 * sc + p * vp[lane];
        o1 = o1 * sc + p * vp[lane + 32];
        m = nm;
        if (did_global) { did_global = false; j = j0; continue; }
        if (++j > i) break;
    }
    float inv = 1.f / l;
    size_t oidx = base + (size_t)i * D;
    float v0 = o0 * inv, v1 = o1 * inv;
    bf16 hi, lo;
    split2(v0, &hi, &lo); Oh[oidx + lane] = hi;      Ol[oidx + lane] = lo;
    split2(v1, &hi, &lo); Oh[oidx + lane + 32] = hi; Ol[oidx + lane + 32] = lo;
}

__global__ void __launch_bounds__(256) attn_last_kernel(
    const float* __restrict__ Q, const float* __restrict__ K,
    const float* __restrict__ V, bf16* __restrict__ Oh, bf16* __restrict__ Ol)
{
    int lane = threadIdx.x & 31;
    int warp = threadIdx.x >> 5;
    int h = blockIdx.x, b = blockIdx.y;
    const int i = T - 1;

    size_t base = (size_t)b * T * D + h * HD;
    const float* qp = Q + base + (size_t)i * D;
    float q0 = qp[lane] * 0.125f, q1 = qp[lane + 32] * 0.125f;

    float m = -1e30f, l = 0.f, o0 = 0.f, o1 = 0.f;
    for (int j = warp; j < T; j += 8) {
        const float* kp = K + base + (size_t)j * D;
        float s = q0 * kp[lane] + q1 * kp[lane + 32];
#pragma unroll
        for (int o = 16; o > 0; o >>= 1) s += __shfl_xor_sync(0xffffffffu, s, o);
        float nm = fmaxf(m, s);
        float sc = __expf(m - nm);
        float p  = __expf(s - nm);
        const float* vp = V + base + (size_t)j * D;
        l  = l  * sc + p;
        o0 = o0 * sc + p * vp[lane];
        o1 = o1 * sc + p * vp[lane + 32];
        m = nm;
    }
    __shared__ float sm[8], sl[8], so[8][64];
    if (lane == 0) { sm[warp] = m; sl[warp] = l; }
    so[warp][lane] = o0; so[warp][lane + 32] = o1;
    __syncthreads();
    if (warp == 0) {
        float gm = -1e30f;
#pragma unroll
        for (int w = 0; w < 8; w++) gm = fmaxf(gm, sm[w]);
        float gl = 0.f, a0 = 0.f, a1 = 0.f;
#pragma unroll
        for (int w = 0; w < 8; w++) {
            float sc = __expf(sm[w] - gm);
            gl += sc * sl[w];
            a0 += sc * so[w][lane];
            a1 += sc * so[w][lane + 32];
        }
        float inv = 1.f / gl;
        size_t oidx = base + (size_t)i * D;
        float v0 = a0 * inv, v1 = a1 * inv;
        bf16 hi, lo;
        split2(v0, &hi, &lo); Oh[oidx + lane] = hi;      Ol[oidx + lane] = lo;
        split2(v1, &hi, &lo); Oh[oidx + lane + 32] = hi; Ol[oidx + lane + 32] = lo;
    }
}

// ---------------- launch ----------------
extern "C" void kernel_launch(void* const* d_in, const int* in_sizes, int n_in,
                              void* d_out, int out_size)
{
    const float* x    = (const float*)d_in[0];
    const float* ln1g = (const float*)d_in[1];
    const float* ln1b = (const float*)d_in[2];
    const float* ln2g = (const float*)d_in[3];
    const float* ln2b = (const float*)d_in[4];
    const float* Wq   = (const float*)d_in[5];
    const float* Wk   = (const float*)d_in[6];
    const float* Wv   = (const float*)d_in[7];
    const float* Wo   = (const float*)d_in[8];
    const float* bo   = (const float*)d_in[9];
    const float* W1   = (const float*)d_in[10];
    const float* b1   = (const float*)d_in[11];
    const float* W2   = (const float*)d_in[12];
    const float* b2   = (const float*)d_in[13];
    float* out = (float*)d_out;

    cudaFuncSetAttribute(mm_kernel,  cudaFuncAttributeMaxDynamicSharedMemorySize, MM_SMEM);
    cudaFuncSetAttribute(qkv_kernel, cudaFuncAttributeMaxDynamicSharedMemorySize, MM_SMEM);

    float *q, *k, *v, *x2;
    bf16 *hh, *hl, *ah, *al, *h2h, *h2l, *f1h, *f1l;
    bf16 *WqTh, *WqTl, *WkTh, *WkTl, *WvTh, *WvTl, *WoTh, *WoTl, *W1Th, *W1Tl, *W2Th, *W2Tl;
    cudaGetSymbolAddress((void**)&q,   g_q);
    cudaGetSymbolAddress((void**)&k,   g_k);
    cudaGetSymbolAddress((void**)&v,   g_v);
    cudaGetSymbolAddress((void**)&x2,  g_x2);
    cudaGetSymbolAddress((void**)&hh,  g_hh);  cudaGetSymbolAddress((void**)&hl,  g_hl);
    cudaGetSymbolAddress((void**)&ah,  g_ah);  cudaGetSymbolAddress((void**)&al,  g_al);
    cudaGetSymbolAddress((void**)&h2h, g_h2h); cudaGetSymbolAddress((void**)&h2l, g_h2l);
    cudaGetSymbolAddress((void**)&f1h, g_f1h); cudaGetSymbolAddress((void**)&f1l, g_f1l);
    cudaGetSymbolAddress((void**)&WqTh, g_WqTh); cudaGetSymbolAddress((void**)&WqTl, g_WqTl);
    cudaGetSymbolAddress((void**)&WkTh, g_WkTh); cudaGetSymbolAddress((void**)&WkTl, g_WkTl);
    cudaGetSymbolAddress((void**)&WvTh, g_WvTh); cudaGetSymbolAddress((void**)&WvTl, g_WvTl);
    cudaGetSymbolAddress((void**)&WoTh, g_WoTh); cudaGetSymbolAddress((void**)&WoTl, g_WoTl);
    cudaGetSymbolAddress((void**)&W1Th, g_W1Th); cudaGetSymbolAddress((void**)&W1Tl, g_W1Tl);
    cudaGetSymbolAddress((void**)&W2Th, g_W2Th); cudaGetSymbolAddress((void**)&W2Tl, g_W2Tl);

    dim3 tb(32, 8);
    tsplit_kernel<<<dim3(D / 32, D / 32), tb>>>(Wq, WqTh, WqTl, D, D);
    tsplit_kernel<<<dim3(D / 32, D / 32), tb>>>(Wk, WkTh, WkTl, D, D);
    tsplit_kernel<<<dim3(D / 32, D / 32), tb>>>(Wv, WvTh, WvTl, D, D);
    tsplit_kernel<<<dim3(D / 32, D / 32), tb>>>(Wo, WoTh, WoTl, D, D);
    tsplit_kernel<<<dim3(DFF / 32, D / 32), tb>>>(W1, W1Th, W1Tl, D, DFF);
    tsplit_kernel<<<dim3(D / 32, DFF / 32), tb>>>(W2, W2Th, W2Tl, DFF, D);

    // 1. h = LN1(x)
    ln_kernel<<<NT, 256>>>(x, ln1g, ln1b, hh, hl);

    // 2. fused QKV: 24 x 16 CTAs
    qkv_kernel<<<dim3(24, NT / 256), 256, MM_SMEM>>>(hh, hl,
        WqTh, WqTl, q, WkTh, WkTl, k, WvTh, WvTl, v);

    // 3. sparse attention
    attn_kernel<<<dim3(T / 4, NH, Bsz), 128>>>(q, k, v, ah, al);
    attn_last_kernel<<<dim3(NH, Bsz), 256>>>(q, k, v, ah, al);

    // 4. x2 = x + att @ Wo + bo
    dim3 gD(D / 128, NT / 256);
    mm_kernel<<<gD, 256, MM_SMEM>>>(ah, al, WoTh, WoTl, bo, x, x2, nullptr, nullptr, D, D, 0);

    // 5. h2 = LN2(x2)
    ln_kernel<<<NT, 256>>>(x2, ln2g, ln2b, h2h, h2l);

    // 6. f1 = gelu(h2 @ W1 + b1)
    dim3 gF(DFF / 128, NT / 256);
    mm_kernel<<<gF, 256, MM_SMEM>>>(h2h, h2l, W1Th, W1Tl, b1, nullptr, nullptr, f1h, f1l, D, DFF, 1);

    // 7. out = x2 + f1 @ W2 + b2
    mm_kernel<<<gD, 256, MM_SMEM>>>(f1h, f1l, W2Th, W2Tl, b2, x2, out, nullptr, nullptr, DFF, D, 0);
}

// round 8
// speedup vs baseline: 2.7672x; 1.3815x over previous
#include <cuda_runtime.h>
#include <cuda_fp16.h>
#include <math.h>
#include <stdint.h>

#define Bsz 2
#define T 2048
#define D 1024
#define NH 16
#define HD 64
#define NT (Bsz*T)    /* 4096 rows */
#define DFF 4096

// ---------------- scratch ----------------
__device__ float g_q [NT*D];
__device__ float g_k [NT*D];
__device__ float g_v [NT*D];
__device__ float g_x2[NT*D];

__device__ half g_hh [NT*D],  g_hl [NT*D];          // LN1 out pair
__device__ half g_ah [NT*D],  g_al [NT*D];          // attention out pair
__device__ half g_h2h[NT*D],  g_h2l[NT*D];          // LN2 out pair
__device__ half g_f1h[(size_t)NT*DFF], g_f1l[(size_t)NT*DFF];   // FFN mid pair

__device__ half g_WqT[D*D];
__device__ half g_WkT[D*D];
__device__ half g_WvT[D*D];
__device__ half g_WoT[D*D];
__device__ half g_W1T[(size_t)D*DFF];   // [DFF, D]
__device__ half g_W2T[(size_t)D*DFF];   // [D, DFF]

// ---------------- helpers ----------------
__device__ __forceinline__ uint32_t s2u(const void* p) {
    uint32_t a;
    asm("{ .reg .u64 t; cvta.to.shared.u64 t, %1; cvt.u32.u64 %0, t; }" : "=r"(a) : "l"(p));
    return a;
}
__device__ __forceinline__ void cp16(uint32_t d, const void* s) {
    asm volatile("cp.async.cg.shared.global [%0], [%1], 16;" :: "r"(d), "l"(s));
}
__device__ __forceinline__ void ldm4(uint32_t* r, uint32_t addr) {
    asm volatile("ldmatrix.sync.aligned.m8n8.x4.shared.b16 {%0,%1,%2,%3}, [%4];"
        : "=r"(r[0]), "=r"(r[1]), "=r"(r[2]), "=r"(r[3]) : "r"(addr));
}
__device__ __forceinline__ void mma_fp16(float* d, const uint32_t* a, const uint32_t* b) {
    asm volatile("mma.sync.aligned.m16n8k16.row.col.f32.f16.f16.f32 "
        "{%0,%1,%2,%3}, {%4,%5,%6,%7}, {%8,%9}, {%0,%1,%2,%3};"
        : "+f"(d[0]), "+f"(d[1]), "+f"(d[2]), "+f"(d[3])
        : "r"(a[0]), "r"(a[1]), "r"(a[2]), "r"(a[3]), "r"(b[0]), "r"(b[1]));
}
__device__ __forceinline__ void split2h(float v, half* hi, half* lo) {
    half h = __float2half_rn(v);
    *hi = h;
    *lo = __float2half_rn(v - __half2float(h));
}

// ---------------- LayerNorm: one block per row, writes fp16 hi/lo pair ----------------
__global__ void __launch_bounds__(256) ln_kernel(const float* __restrict__ x,
                                                 const float* __restrict__ gam,
                                                 const float* __restrict__ bet,
                                                 half* __restrict__ oh,
                                                 half* __restrict__ ol)
{
    int row = blockIdx.x;
    const float* xr = x + (size_t)row * D;
    int tid = threadIdx.x;

    float v[4];
    float s = 0.f, s2 = 0.f;
#pragma unroll
    for (int i = 0; i < 4; i++) {
        v[i] = xr[tid + i * 256];
        s  += v[i];
        s2 += v[i] * v[i];
    }
#pragma unroll
    for (int o = 16; o > 0; o >>= 1) {
        s  += __shfl_xor_sync(0xffffffffu, s,  o);
        s2 += __shfl_xor_sync(0xffffffffu, s2, o);
    }
    __shared__ float sh[2][8];
    int w = tid >> 5, l = tid & 31;
    if (l == 0) { sh[0][w] = s; sh[1][w] = s2; }
    __syncthreads();
    float ts = 0.f, ts2 = 0.f;
#pragma unroll
    for (int i = 0; i < 8; i++) { ts += sh[0][i]; ts2 += sh[1][i]; }
    float mean = ts * (1.0f / D);
    float var  = ts2 * (1.0f / D) - mean * mean;
    float inv  = rsqrtf(var + 1e-5f);
#pragma unroll
    for (int i = 0; i < 4; i++) {
        int idx = tid + i * 256;
        float vv = (v[i] - mean) * inv * gam[idx] + bet[idx];
        size_t o = (size_t)row * D + idx;
        half hi, lo; split2h(vv, &hi, &lo);
        oh[o] = hi; ol[o] = lo;
    }
}

// ---------------- transpose + convert: W[K,N] fp32 -> T [N,K] fp16 ----------------
__global__ void __launch_bounds__(256) tcvt_kernel(const float* __restrict__ W,
                                                   half* __restrict__ Th,
                                                   int K, int N)
{
    __shared__ float t[32][33];
    int n0 = blockIdx.x * 32, k0 = blockIdx.y * 32;
    int tx = threadIdx.x, ty = threadIdx.y;
#pragma unroll
    for (int j = 0; j < 4; j++)
        t[ty + j * 8][tx] = W[(size_t)(k0 + ty + j * 8) * N + n0 + tx];
    __syncthreads();
#pragma unroll
    for (int j = 0; j < 4; j++) {
        float v = t[tx][ty + j * 8];
        size_t o = (size_t)(n0 + ty + j * 8) * K + k0 + tx;
        Th[o] = __float2half_rn(v);
    }
}

// ---------------- fp16x2 HMMA GEMM core ----------------
// C = act((Ah+Al) @ Bh^T + bias) + res
// CTA tile 256x128, 8 warps, warp tile 64x64 (wm=warp&3, wn=warp>>2), BK=32.
// smem stage: A-hi[256x80B] + A-lo[256x80B] + B[128x80B] = 51200 B; double buffered.
#define STG 51200
#define MM_SMEM (2 * STG)

__device__ __forceinline__ void mm_body(
    const half* __restrict__ Ah, const half* __restrict__ Al,
    const half* __restrict__ Bh,
    const float* __restrict__ bias, const float* __restrict__ res,
    float* __restrict__ Cf, half* __restrict__ Ch, half* __restrict__ Cl,
    int K, int N, int gelu_flag, int bm, int bnc, char* smem)
{
    uint32_t sb = s2u(smem);
    int tid = threadIdx.x, warp = tid >> 5, lane = tid & 31;
    int wm = warp & 3, wn = warp >> 2;
    const int nchunk = K / 32;

    int lr = tid >> 2;          // 0..63
    int cb = (tid & 3) * 16;    // byte chunk in a 64B k-slab

    auto load_stage = [&](int st, int c) {
        uint32_t base = sb + st * STG;
        size_t ko = (size_t)c * 64 + cb;
#pragma unroll
        for (int i = 0; i < 4; i++) {
            int r = lr + i * 64;
            size_t g = ((size_t)(bm * 256 + r) * K) * 2 + ko;
            uint32_t s = base + r * 80 + cb;
            cp16(s,         (const char*)Ah + g);
            cp16(s + 20480, (const char*)Al + g);
        }
#pragma unroll
        for (int i = 0; i < 2; i++) {
            int r = lr + i * 64;
            size_t g = ((size_t)(bnc * 128 + r) * K) * 2 + ko;
            cp16(base + 40960 + r * 80 + cb, (const char*)Bh + g);
        }
    };

    float acc[4][8][4];
#pragma unroll
    for (int i = 0; i < 4; i++)
#pragma unroll
        for (int j = 0; j < 8; j++)
#pragma unroll
            for (int r = 0; r < 4; r++) acc[i][j][r] = 0.f;

    load_stage(0, 0);
    asm volatile("cp.async.commit_group;" ::: "memory");

    int a_row = wm * 64 + (lane & 15);
    int a_kb  = (lane >> 4) * 16;
    int b_row = wn * 64 + (lane & 7) + ((lane >> 4) << 3);
    int b_kb  = ((lane >> 3) & 1) * 16;

    for (int it = 0; it < nchunk; it++) {
        if (it + 1 < nchunk) {
            load_stage((it + 1) & 1, it + 1);
            asm volatile("cp.async.commit_group;" ::: "memory");
            asm volatile("cp.async.wait_group 1;" ::: "memory");
        } else {
            asm volatile("cp.async.wait_group 0;" ::: "memory");
        }
        __syncthreads();

        uint32_t stb = sb + (it & 1) * STG;
#pragma unroll
        for (int ks = 0; ks < 2; ks++) {
            uint32_t aH[4][4], aL[4][4];
#pragma unroll
            for (int mt = 0; mt < 4; mt++) {
                uint32_t ad = stb + (a_row + mt * 16) * 80 + ks * 32 + a_kb;
                ldm4(aH[mt], ad);
                ldm4(aL[mt], ad + 20480);
            }
#pragma unroll
            for (int np = 0; np < 4; np++) {
                uint32_t bh[4];
                uint32_t bd = stb + 40960 + (b_row + np * 16) * 80 + ks * 32 + b_kb;
                ldm4(bh, bd);
#pragma unroll
                for (int mt = 0; mt < 4; mt++) {
                    mma_fp16(acc[mt][np * 2],     aH[mt], bh);
                    mma_fp16(acc[mt][np * 2],     aL[mt], bh);
                    mma_fp16(acc[mt][np * 2 + 1], aH[mt], bh + 2);
                    mma_fp16(acc[mt][np * 2 + 1], aL[mt], bh + 2);
                }
            }
        }
        __syncthreads();
    }

    // ---- epilogue ----
    int qr = lane >> 2, qc = (lane & 3) * 2;
#pragma unroll
    for (int mt = 0; mt < 4; mt++) {
#pragma unroll
        for (int nt = 0; nt < 8; nt++) {
            int col = bnc * 128 + wn * 64 + nt * 8 + qc;
            float b0 = bias ? bias[col] : 0.f;
            float b1 = bias ? bias[col + 1] : 0.f;
#pragma unroll
            for (int half_i = 0; half_i < 2; half_i++) {
                size_t row = (size_t)bm * 256 + wm * 64 + mt * 16 + qr + half_i * 8;
                float v0 = acc[mt][nt][half_i * 2]     + b0;
                float v1 = acc[mt][nt][half_i * 2 + 1] + b1;
                if (gelu_flag) {
                    v0 = 0.5f * v0 * (1.0f + erff(v0 * 0.70710678118654752f));
                    v1 = 0.5f * v1 * (1.0f + erff(v1 * 0.70710678118654752f));
                }
                size_t idx = row * (size_t)N + col;
                if (res) { v0 += res[idx]; v1 += res[idx + 1]; }
                if (Cf) {
                    *(float2*)(Cf + idx) = make_float2(v0, v1);
                } else {
                    half h0, l0, h1, l1;
                    split2h(v0, &h0, &l0); split2h(v1, &h1, &l1);
                    *(__half2*)(Ch + idx) = __halves2half2(h0, h1);
                    *(__half2*)(Cl + idx) = __halves2half2(l0, l1);
                }
            }
        }
    }
}

__global__ void __launch_bounds__(256, 1) mm_kernel(
    const half* __restrict__ Ah, const half* __restrict__ Al,
    const half* __restrict__ Bh,
    const float* __restrict__ bias, const float* __restrict__ res,
    float* __restrict__ Cf, half* __restrict__ Ch, half* __restrict__ Cl,
    int K, int N, int gelu_flag)
{
    extern __shared__ char smem[];
    mm_body(Ah, Al, Bh, bias, res, Cf, Ch, Cl, K, N, gelu_flag,
            blockIdx.y, blockIdx.x, smem);
}

// Fused QKV: blockIdx.x in [0,24): sel = x>>3 picks {Wq,Wk,Wv} and {q,k,v}.
__global__ void __launch_bounds__(256, 1) qkv_kernel(
    const half* __restrict__ Ah, const half* __restrict__ Al,
    const half* __restrict__ Bq, float* __restrict__ Cq,
    const half* __restrict__ Bk, float* __restrict__ Ck,
    const half* __restrict__ Bv, float* __restrict__ Cv)
{
    extern __shared__ char smem[];
    int sel = blockIdx.x >> 3, bnc = blockIdx.x & 7;
    const half* Bh = (sel == 0) ? Bq : (sel == 1) ? Bk : Bv;
    float* Cf      = (sel == 0) ? Cq : (sel == 1) ? Ck : Cv;
    mm_body(Ah, Al, Bh, nullptr, nullptr, Cf, nullptr, nullptr, D, D, 0,
            blockIdx.y, bnc, smem);
}

// ---------------- Attention (Longformer sparse, causal), 2-way unrolled ----------------
__global__ void __launch_bounds__(128) attn_kernel(
    const float* __restrict__ Q, const float* __restrict__ K,
    const float* __restrict__ V, half* __restrict__ Oh, half* __restrict__ Ol)
{
    int lane = threadIdx.x & 31;
    int warp = threadIdx.x >> 5;
    int i = blockIdx.x * 4 + warp;
    int h = blockIdx.y, b = blockIdx.z;
    if (i == T - 1) return;

    size_t base = (size_t)b * T * D + h * HD;
    const float* qp = Q + base + (size_t)i * D;
    float q0 = qp[lane] * 0.125f, q1 = qp[lane + 32] * 0.125f;

    float m = -1e30f, l = 0.f, o0 = 0.f, o1 = 0.f;
    int j0 = i - 128; if (j0 < 0) j0 = 0;

    if (j0 > 0) {   // global key 0 outside window
        const float* kp = K + base;
        float s = q0 * kp[lane] + q1 * kp[lane + 32];
#pragma unroll
        for (int o = 16; o > 0; o >>= 1) s += __shfl_xor_sync(0xffffffffu, s, o);
        float nm = fmaxf(m, s);
        float sc = __expf(m - nm);
        float p  = __expf(s - nm);
        const float* vp = V + base;
        l  = l  * sc + p;
        o0 = o0 * sc + p * vp[lane];
        o1 = o1 * sc + p * vp[lane + 32];
        m = nm;
    }

    int j = j0;
    for (; j + 1 <= i; j += 2) {
        const float* kpa = K + base + (size_t)j * D;
        const float* kpb = kpa + D;
        float sa = q0 * kpa[lane] + q1 * kpa[lane + 32];
        float sb = q0 * kpb[lane] + q1 * kpb[lane + 32];
#pragma unroll
        for (int o = 16; o > 0; o >>= 1) {
            sa += __shfl_xor_sync(0xffffffffu, sa, o);
            sb += __shfl_xor_sync(0xffffffffu, sb, o);
        }
        float nm = fmaxf(m, fmaxf(sa, sb));
        float sc = __expf(m - nm);
        float pa = __expf(sa - nm);
        float pb = __expf(sb - nm);
        const float* vpa = V + base + (size_t)j * D;
        const float* vpb = vpa + D;
        l  = l  * sc + pa + pb;
        o0 = o0 * sc + pa * vpa[lane] + pb * vpb[lane];
        o1 = o1 * sc + pa * vpa[lane + 32] + pb * vpb[lane + 32];
        m = nm;
    }
    if (j <= i) {
        const float* kp = K + base + (size_t)j * D;
        float s = q0 * kp[lane] + q1 * kp[lane + 32];
#pragma unroll
        for (int o = 16; o > 0; o >>= 1) s += __shfl_xor_sync(0xffffffffu, s, o);
        float nm = fmaxf(m, s);
        float sc = __expf(m - nm);
        float p  = __expf(s - nm);
        const float* vp = V + base + (size_t)j * D;
        l  = l  * sc + p;
        o0 = o0 * sc + p * vp[lane];
        o1 = o1 * sc + p * vp[lane + 32];
        m = nm;
    }

    float inv = 1.f / l;
    size_t oidx = base + (size_t)i * D;
    float v0 = o0 * inv, v1 = o1 * inv;
    half hi, lo;
    split2h(v0, &hi, &lo); Oh[oidx + lane] = hi;      Ol[oidx + lane] = lo;
    split2h(v1, &hi, &lo); Oh[oidx + lane + 32] = hi; Ol[oidx + lane + 32] = lo;
}

// Dense row i = T-1: 8 warps partition keys (2-way unrolled), log-sum-exp merge.
__global__ void __launch_bounds__(256) attn_last_kernel(
    const float* __restrict__ Q, const float* __restrict__ K,
    const float* __restrict__ V, half* __restrict__ Oh, half* __restrict__ Ol)
{
    int lane = threadIdx.x & 31;
    int warp = threadIdx.x >> 5;
    int h = blockIdx.x, b = blockIdx.y;
    const int i = T - 1;

    size_t base = (size_t)b * T * D + h * HD;
    const float* qp = Q + base + (size_t)i * D;
    float q0 = qp[lane] * 0.125f, q1 = qp[lane + 32] * 0.125f;

    float m = -1e30f, l = 0.f, o0 = 0.f, o1 = 0.f;
    for (int j = warp; j < T; j += 16) {   // T % 16 == 0, pairs (j, j+8)
        const float* kpa = K + base + (size_t)j * D;
        const float* kpb = kpa + (size_t)8 * D;
        float sa = q0 * kpa[lane] + q1 * kpa[lane + 32];
        float sb = q0 * kpb[lane] + q1 * kpb[lane + 32];
#pragma unroll
        for (int o = 16; o > 0; o >>= 1) {
            sa += __shfl_xor_sync(0xffffffffu, sa, o);
            sb += __shfl_xor_sync(0xffffffffu, sb, o);
        }
        float nm = fmaxf(m, fmaxf(sa, sb));
        float sc = __expf(m - nm);
        float pa = __expf(sa - nm);
        float pb = __expf(sb - nm);
        const float* vpa = V + base + (size_t)j * D;
        const float* vpb = vpa + (size_t)8 * D;
        l  = l  * sc + pa + pb;
        o0 = o0 * sc + pa * vpa[lane] + pb * vpb[lane];
        o1 = o1 * sc + pa * vpa[lane + 32] + pb * vpb[lane + 32];
        m = nm;
    }
    __shared__ float sm[8], sl[8], so[8][64];
    if (lane == 0) { sm[warp] = m; sl[warp] = l; }
    so[warp][lane] = o0; so[warp][lane + 32] = o1;
    __syncthreads();
    if (warp == 0) {
        float gm = -1e30f;
#pragma unroll
        for (int w = 0; w < 8; w++) gm = fmaxf(gm, sm[w]);
        float gl = 0.f, a0 = 0.f, a1 = 0.f;
#pragma unroll
        for (int w = 0; w < 8; w++) {
            float sc = __expf(sm[w] - gm);
            gl += sc * sl[w];
            a0 += sc * so[w][lane];
            a1 += sc * so[w][lane + 32];
        }
        float inv = 1.f / gl;
        size_t oidx = base + (size_t)i * D;
        float v0 = a0 * inv, v1 = a1 * inv;
        half hi, lo;
        split2h(v0, &hi, &lo); Oh[oidx + lane] = hi;      Ol[oidx + lane] = lo;
        split2h(v1, &hi, &lo); Oh[oidx + lane + 32] = hi; Ol[oidx + lane + 32] = lo;
    }
}

// ---------------- launch ----------------
extern "C" void kernel_launch(void* const* d_in, const int* in_sizes, int n_in,
                              void* d_out, int out_size)
{
    const float* x    = (const float*)d_in[0];
    const float* ln1g = (const float*)d_in[1];
    const float* ln1b = (const float*)d_in[2];
    const float* ln2g = (const float*)d_in[3];
    const float* ln2b = (const float*)d_in[4];
    const float* Wq   = (const float*)d_in[5];
    const float* Wk   = (const float*)d_in[6];
    const float* Wv   = (const float*)d_in[7];
    const float* Wo   = (const float*)d_in[8];
    const float* bo   = (const float*)d_in[9];
    const float* W1   = (const float*)d_in[10];
    const float* b1   = (const float*)d_in[11];
    const float* W2   = (const float*)d_in[12];
    const float* b2   = (const float*)d_in[13];
    float* out = (float*)d_out;

    cudaFuncSetAttribute(mm_kernel,  cudaFuncAttributeMaxDynamicSharedMemorySize, MM_SMEM);
    cudaFuncSetAttribute(qkv_kernel, cudaFuncAttributeMaxDynamicSharedMemorySize, MM_SMEM);

    float *q, *k, *v, *x2;
    half *hh, *hl, *ah, *al, *h2h, *h2l, *f1h, *f1l;
    half *WqT, *WkT, *WvT, *WoT, *W1T, *W2T;
    cudaGetSymbolAddress((void**)&q,   g_q);
    cudaGetSymbolAddress((void**)&k,   g_k);
    cudaGetSymbolAddress((void**)&v,   g_v);
    cudaGetSymbolAddress((void**)&x2,  g_x2);
    cudaGetSymbolAddress((void**)&hh,  g_hh);  cudaGetSymbolAddress((void**)&hl,  g_hl);
    cudaGetSymbolAddress((void**)&ah,  g_ah);  cudaGetSymbolAddress((void**)&al,  g_al);
    cudaGetSymbolAddress((void**)&h2h, g_h2h); cudaGetSymbolAddress((void**)&h2l, g_h2l);
    cudaGetSymbolAddress((void**)&f1h, g_f1h); cudaGetSymbolAddress((void**)&f1l, g_f1l);
    cudaGetSymbolAddress((void**)&WqT, g_WqT);
    cudaGetSymbolAddress((void**)&WkT, g_WkT);
    cudaGetSymbolAddress((void**)&WvT, g_WvT);
    cudaGetSymbolAddress((void**)&WoT, g_WoT);
    cudaGetSymbolAddress((void**)&W1T, g_W1T);
    cudaGetSymbolAddress((void**)&W2T, g_W2T);

    dim3 tb(32, 8);
    tcvt_kernel<<<dim3(D / 32, D / 32), tb>>>(Wq, WqT, D, D);
    tcvt_kernel<<<dim3(D / 32, D / 32), tb>>>(Wk, WkT, D, D);
    tcvt_kernel<<<dim3(D / 32, D / 32), tb>>>(Wv, WvT, D, D);
    tcvt_kernel<<<dim3(D / 32, D / 32), tb>>>(Wo, WoT, D, D);
    tcvt_kernel<<<dim3(DFF / 32, D / 32), tb>>>(W1, W1T, D, DFF);
    tcvt_kernel<<<dim3(D / 32, DFF / 32), tb>>>(W2, W2T, DFF, D);

    // 1. h = LN1(x)
    ln_kernel<<<NT, 256>>>(x, ln1g, ln1b, hh, hl);

    // 2. fused QKV: 24 x 16 CTAs
    qkv_kernel<<<dim3(24, NT / 256), 256, MM_SMEM>>>(hh, hl, WqT, q, WkT, k, WvT, v);

    // 3. sparse attention
    attn_kernel<<<dim3(T / 4, NH, Bsz), 128>>>(q, k, v, ah, al);
    attn_last_kernel<<<dim3(NH, Bsz), 256>>>(q, k, v, ah, al);

    // 4. x2 = x + att @ Wo + bo
    dim3 gD(D / 128, NT / 256);
    mm_kernel<<<gD, 256, MM_SMEM>>>(ah, al, WoT, bo, x, x2, nullptr, nullptr, D, D, 0);

    // 5. h2 = LN2(x2)
    ln_kernel<<<NT, 256>>>(x2, ln2g, ln2b, h2h, h2l);

    // 6. f1 = gelu(h2 @ W1 + b1)
    dim3 gF(DFF / 128, NT / 256);
    mm_kernel<<<gF, 256, MM_SMEM>>>(h2h, h2l, W1T, b1, nullptr, nullptr, f1h, f1l, D, DFF, 1);

    // 7. out = x2 + f1 @ W2 + b2
    mm_kernel<<<gD, 256, MM_SMEM>>>(f1h, f1l, W2T, b2, x2, out, nullptr, nullptr, DFF, D, 0);
}

// round 10
// speedup vs baseline: 4.2845x; 1.5483x over previous
#include <cuda_runtime.h>
#include <cuda_fp16.h>
#include <math.h>
#include <stdint.h>

#define Bsz 2
#define T 2048
#define D 1024
#define NH 16
#define HD 64
#define NT (Bsz*T)    /* 4096 rows */
#define DFF 4096

// ---------------- scratch ----------------
__device__ float g_q [NT*D];
__device__ float g_k [NT*D];
__device__ float g_v [NT*D];
__device__ float g_x2[NT*D];

__device__ half g_h  [NT*D];          // LN1 out
__device__ half g_a  [NT*D];          // attention out
__device__ half g_h2 [NT*D];          // LN2 out
__device__ half g_f1 [(size_t)NT*DFF];// FFN mid

__device__ half g_WqT[D*D];
__device__ half g_WkT[D*D];
__device__ half g_WvT[D*D];
__device__ half g_WoT[D*D];
__device__ half g_W1T[(size_t)D*DFF];   // [DFF, D]
__device__ half g_W2T[(size_t)D*DFF];   // [D, DFF]

// ---------------- helpers ----------------
__device__ __forceinline__ uint32_t s2u(const void* p) {
    uint32_t a;
    asm("{ .reg .u64 t; cvta.to.shared.u64 t, %1; cvt.u32.u64 %0, t; }" : "=r"(a) : "l"(p));
    return a;
}
__device__ __forceinline__ void cp16(uint32_t d, const void* s) {
    asm volatile("cp.async.cg.shared.global [%0], [%1], 16;" :: "r"(d), "l"(s));
}
__device__ __forceinline__ void ldm4(uint32_t* r, uint32_t addr) {
    asm volatile("ldmatrix.sync.aligned.m8n8.x4.shared.b16 {%0,%1,%2,%3}, [%4];"
        : "=r"(r[0]), "=r"(r[1]), "=r"(r[2]), "=r"(r[3]) : "r"(addr));
}
__device__ __forceinline__ void mma_fp16(float* d, const uint32_t* a, const uint32_t* b) {
    asm volatile("mma.sync.aligned.m16n8k16.row.col.f32.f16.f16.f32 "
        "{%0,%1,%2,%3}, {%4,%5,%6,%7}, {%8,%9}, {%0,%1,%2,%3};"
        : "+f"(d[0]), "+f"(d[1]), "+f"(d[2]), "+f"(d[3])
        : "r"(a[0]), "r"(a[1]), "r"(a[2]), "r"(a[3]), "r"(b[0]), "r"(b[1]));
}

// ---------------- LayerNorm: one block per row, writes fp16 ----------------
__global__ void __launch_bounds__(256) ln_kernel(const float* __restrict__ x,
                                                 const float* __restrict__ gam,
                                                 const float* __restrict__ bet,
                                                 half* __restrict__ oh)
{
    int row = blockIdx.x;
    const float* xr = x + (size_t)row * D;
    int tid = threadIdx.x;

    float v[4];
    float s = 0.f, s2 = 0.f;
#pragma unroll
    for (int i = 0; i < 4; i++) {
        v[i] = xr[tid + i * 256];
        s  += v[i];
        s2 += v[i] * v[i];
    }
#pragma unroll
    for (int o = 16; o > 0; o >>= 1) {
        s  += __shfl_xor_sync(0xffffffffu, s,  o);
        s2 += __shfl_xor_sync(0xffffffffu, s2, o);
    }
    __shared__ float sh[2][8];
    int w = tid >> 5, l = tid & 31;
    if (l == 0) { sh[0][w] = s; sh[1][w] = s2; }
    __syncthreads();
    float ts = 0.f, ts2 = 0.f;
#pragma unroll
    for (int i = 0; i < 8; i++) { ts += sh[0][i]; ts2 += sh[1][i]; }
    float mean = ts * (1.0f / D);
    float var  = ts2 * (1.0f / D) - mean * mean;
    float inv  = rsqrtf(var + 1e-5f);
#pragma unroll
    for (int i = 0; i < 4; i++) {
        int idx = tid + i * 256;
        float vv = (v[i] - mean) * inv * gam[idx] + bet[idx];
        oh[(size_t)row * D + idx] = __float2half_rn(vv);
    }
}

// ---------------- transpose + convert: W[K,N] fp32 -> T [N,K] fp16 ----------------
__global__ void __launch_bounds__(256) tcvt_kernel(const float* __restrict__ W,
                                                   half* __restrict__ Th,
                                                   int K, int N)
{
    __shared__ float t[32][33];
    int n0 = blockIdx.x * 32, k0 = blockIdx.y * 32;
    int tx = threadIdx.x, ty = threadIdx.y;
#pragma unroll
    for (int j = 0; j < 4; j++)
        t[ty + j * 8][tx] = W[(size_t)(k0 + ty + j * 8) * N + n0 + tx];
    __syncthreads();
#pragma unroll
    for (int j = 0; j < 4; j++) {
        float v = t[tx][ty + j * 8];
        Th[(size_t)(n0 + ty + j * 8) * K + k0 + tx] = __float2half_rn(v);
    }
}

// fused 4x D x D transpose: blockIdx.z selects weight
__global__ void __launch_bounds__(256) tcvt4_kernel(
    const float* __restrict__ W0, half* __restrict__ T0,
    const float* __restrict__ W1, half* __restrict__ T1,
    const float* __restrict__ W2, half* __restrict__ T2,
    const float* __restrict__ W3, half* __restrict__ T3)
{
    const float* W = (blockIdx.z == 0) ? W0 : (blockIdx.z == 1) ? W1 : (blockIdx.z == 2) ? W2 : W3;
    half*       Th = (blockIdx.z == 0) ? T0 : (blockIdx.z == 1) ? T1 : (blockIdx.z == 2) ? T2 : T3;
    __shared__ float t[32][33];
    int n0 = blockIdx.x * 32, k0 = blockIdx.y * 32;
    int tx = threadIdx.x, ty = threadIdx.y;
#pragma unroll
    for (int j = 0; j < 4; j++)
        t[ty + j * 8][tx] = W[(size_t)(k0 + ty + j * 8) * D + n0 + tx];
    __syncthreads();
#pragma unroll
    for (int j = 0; j < 4; j++) {
        float v = t[tx][ty + j * 8];
        Th[(size_t)(n0 + ty + j * 8) * D + k0 + tx] = __float2half_rn(v);
    }
}

// ---------------- fp16 single-pass HMMA GEMM core ----------------
// C = act(A @ B^T + bias) + res ; A [M,K] fp16, B [N,K] fp16.
// CTA 256x128, 8 warps 64x64, BK=32, 3-stage cp.async pipeline.
// stage: A 256x80B (20480) + B 128x80B (10240) = 30720 B.
#define STG 30720
#define MM_SMEM (3 * STG)

__device__ __forceinline__ void mm_body(
    const half* __restrict__ Ah, const half* __restrict__ Bh,
    const float* __restrict__ bias, const float* __restrict__ res,
    float* __restrict__ Cf, half* __restrict__ Ch,
    int K, int N, int gelu_flag, int bm, int bnc, char* smem)
{
    uint32_t sb = s2u(smem);
    int tid = threadIdx.x, warp = tid >> 5, lane = tid & 31;
    int wm = warp & 3, wn = warp >> 2;
    const int nchunk = K / 32;

    int lr = tid >> 2;          // 0..63
    int cb = (tid & 3) * 16;    // byte chunk in a 64B k-slab

    auto load_stage = [&](int st, int c) {
        uint32_t base = sb + st * STG;
        size_t ko = (size_t)c * 64 + cb;
#pragma unroll
        for (int i = 0; i < 4; i++) {
            int r = lr + i * 64;
            cp16(base + r * 80 + cb, (const char*)Ah + ((size_t)(bm * 256 + r) * K) * 2 + ko);
        }
#pragma unroll
        for (int i = 0; i < 2; i++) {
            int r = lr + i * 64;
            cp16(base + 20480 + r * 80 + cb, (const char*)Bh + ((size_t)(bnc * 128 + r) * K) * 2 + ko);
        }
    };

    float acc[4][8][4];
#pragma unroll
    for (int i = 0; i < 4; i++)
#pragma unroll
        for (int j = 0; j < 8; j++)
#pragma unroll
            for (int r = 0; r < 4; r++) acc[i][j][r] = 0.f;

    load_stage(0, 0); asm volatile("cp.async.commit_group;" ::: "memory");
    load_stage(1, 1); asm volatile("cp.async.commit_group;" ::: "memory");

    int a_row = wm * 64 + (lane & 15);
    int a_kb  = (lane >> 4) * 16;
    int b_row = wn * 64 + (lane & 7) + ((lane >> 4) << 3);
    int b_kb  = ((lane >> 3) & 1) * 16;

    for (int it = 0; it < nchunk; it++) {
        asm volatile("cp.async.wait_group 1;" ::: "memory");
        __syncthreads();
        if (it + 2 < nchunk) load_stage((it + 2) % 3, it + 2);
        asm volatile("cp.async.commit_group;" ::: "memory");

        uint32_t stb = sb + (it % 3) * STG;
#pragma unroll
        for (int ks = 0; ks < 2; ks++) {
            uint32_t aH[4][4];
#pragma unroll
            for (int mt = 0; mt < 4; mt++)
                ldm4(aH[mt], stb + (a_row + mt * 16) * 80 + ks * 32 + a_kb);
#pragma unroll
            for (int np = 0; np < 4; np++) {
                uint32_t bh[4];
                ldm4(bh, stb + 20480 + (b_row + np * 16) * 80 + ks * 32 + b_kb);
#pragma unroll
                for (int mt = 0; mt < 4; mt++) {
                    mma_fp16(acc[mt][np * 2],     aH[mt], bh);
                    mma_fp16(acc[mt][np * 2 + 1], aH[mt], bh + 2);
                }
            }
        }
        __syncthreads();
    }

    // ---- epilogue ----
    int qr = lane >> 2, qc = (lane & 3) * 2;
#pragma unroll
    for (int mt = 0; mt < 4; mt++) {
#pragma unroll
        for (int nt = 0; nt < 8; nt++) {
            int col = bnc * 128 + wn * 64 + nt * 8 + qc;
            float b0 = bias ? bias[col] : 0.f;
            float b1 = bias ? bias[col + 1] : 0.f;
#pragma unroll
            for (int hf = 0; hf < 2; hf++) {
                size_t row = (size_t)bm * 256 + wm * 64 + mt * 16 + qr + hf * 8;
                float v0 = acc[mt][nt][hf * 2]     + b0;
                float v1 = acc[mt][nt][hf * 2 + 1] + b1;
                if (gelu_flag) {
                    v0 = 0.5f * v0 * (1.0f + erff(v0 * 0.70710678118654752f));
                    v1 = 0.5f * v1 * (1.0f + erff(v1 * 0.70710678118654752f));
                }
                size_t idx = row * (size_t)N + col;
                if (res) { v0 += res[idx]; v1 += res[idx + 1]; }
                if (Cf) {
                    *(float2*)(Cf + idx) = make_float2(v0, v1);
                } else {
                    *(__half2*)(Ch + idx) = __halves2half2(__float2half_rn(v0), __float2half_rn(v1));
                }
            }
        }
    }
}

__global__ void __launch_bounds__(256, 1) mm_kernel(
    const half* __restrict__ Ah, const half* __restrict__ Bh,
    const float* __restrict__ bias, const float* __restrict__ res,
    float* __restrict__ Cf, half* __restrict__ Ch,
    int K, int N, int gelu_flag)
{
    extern __shared__ char smem[];
    mm_body(Ah, Bh, bias, res, Cf, Ch, K, N, gelu_flag, blockIdx.y, blockIdx.x, smem);
}

__global__ void __launch_bounds__(256, 1) qkv_kernel(
    const half* __restrict__ Ah,
    const half* __restrict__ Bq, float* __restrict__ Cq,
    const half* __restrict__ Bk, float* __restrict__ Ck,
    const half* __restrict__ Bv, float* __restrict__ Cv)
{
    extern __shared__ char smem[];
    int sel = blockIdx.x >> 3, bnc = blockIdx.x & 7;
    const half* Bh = (sel == 0) ? Bq : (sel == 1) ? Bk : Bv;
    float* Cf      = (sel == 0) ? Cq : (sel == 1) ? Ck : Cv;
    mm_body(Ah, Bh, nullptr, nullptr, Cf, nullptr, D, D, 0, blockIdx.y, bnc, smem);
}

// ---------------- Attention: smem-tiled, 64 queries per CTA ----------------
// smem layout (bytes): Ks[192*65 f] @0, Vs[195*66 f] @49920, k0s[64] @101408,
// v0s[64] @101664, ps[8][160] @101920. Total 107040.
#define KS_OFF   0
#define VS_OFF   49920
#define K0_OFF   101408
#define V0_OFF   101664
#define PS_OFF   101920
#define ATTN_SMEM 107040

__global__ void __launch_bounds__(256, 1) attn_tile_kernel(
    const float* __restrict__ Q, const float* __restrict__ K,
    const float* __restrict__ V, half* __restrict__ O)
{
    extern __shared__ char smem[];
    float* Ks  = (float*)(smem + KS_OFF);   // [r*65 + d]
    float* Vs  = (float*)(smem + VS_OFF);   // [r*66 + d]
    float* k0s = (float*)(smem + K0_OFF);
    float* v0s = (float*)(smem + V0_OFF);
    float* ps  = (float*)(smem + PS_OFF);   // [warp*160 + kk]

    int tid = threadIdx.x, warp = tid >> 5, lane = tid & 31;
    int q0 = blockIdx.x * 64;
    int h = blockIdx.y, b = blockIdx.z;
    size_t base = (size_t)b * T * D + h * HD;

    int kLo = q0 - 128; if (kLo < 0) kLo = 0;
    int R = q0 + 64 - kLo;                 // <= 192

    for (int idx = tid; idx < R * 64; idx += 256) {
        int r = idx >> 6, d = idx & 63;
        Ks[r * 65 + d] = K[base + (size_t)(kLo + r) * D + d];
        Vs[r * 66 + d] = V[base + (size_t)(kLo + r) * D + d];
    }
    if (tid < 64) {
        k0s[tid] = K[base + tid];
        v0s[tid] = V[base + tid];
    }
    __syncthreads();

    float* pw = ps + warp * 160;
    int d0 = 2 * lane, d1 = 2 * lane + 1;

    for (int qq = 0; qq < 8; qq++) {
        int i = q0 + warp * 8 + qq;
        if (i == T - 1) continue;   // dense row handled separately

        // q into registers (uniform-address loads, L1 broadcast)
        float qreg[64];
        const float4* qp4 = (const float4*)(Q + base + (size_t)i * D);
#pragma unroll
        for (int t = 0; t < 16; t++) {
            float4 f = qp4[t];
            qreg[4 * t] = f.x; qreg[4 * t + 1] = f.y; qreg[4 * t + 2] = f.z; qreg[4 * t + 3] = f.w;
        }

        int jLo = i - 128; if (jLo < 0) jLo = 0;
        int nk = i - jLo + 1;          // <= 129
        int rBase = jLo - kLo;         // >= 0

        // phase 1: scores (lanes over keys)
        float sc[5];
        float mloc = -1e30f;
#pragma unroll
        for (int bq = 0; bq < 5; bq++) {
            int kk = lane + bq * 32;
            float s = -1e30f;
            if (kk < nk) {
                const float* kr = Ks + (rBase + kk) * 65;
                s = 0.f;
#pragma unroll
                for (int d = 0; d < 64; d++) s += qreg[d] * kr[d];
                s *= 0.125f;
            }
            sc[bq] = s;
            mloc = fmaxf(mloc, s);
        }
        float s0 = -1e30f;
        if (jLo > 0) {                  // global key 0 outside window
            s0 = 0.f;
#pragma unroll
            for (int d = 0; d < 64; d++) s0 += qreg[d] * k0s[d];
            s0 *= 0.125f;
            mloc = fmaxf(mloc, s0);
        }
#pragma unroll
        for (int o = 16; o > 0; o >>= 1) mloc = fmaxf(mloc, __shfl_xor_sync(0xffffffffu, mloc, o));

        float lloc = 0.f;
#pragma unroll
        for (int bq = 0; bq < 5; bq++) {
            float p = __expf(sc[bq] - mloc);    // underflows to 0 for masked
            pw[lane + bq * 32] = p;
            lloc += p;
        }
        float p0 = 0.f;
        if (jLo > 0) {
            p0 = __expf(s0 - mloc);
            if (lane == 0) lloc += p0;
        }
#pragma unroll
        for (int o = 16; o > 0; o >>= 1) lloc += __shfl_xor_sync(0xffffffffu, lloc, o);
        __syncwarp();

        // phase 2: output accumulation, dims (2*lane, 2*lane+1)
        float o0 = (jLo > 0) ? p0 * v0s[d0] : 0.f;
        float o1 = (jLo > 0) ? p0 * v0s[d1] : 0.f;
        for (int kk = 0; kk < nk; kk += 4) {
            float4 p4 = *(float4*)(pw + kk);
            float pv[4] = {p4.x, p4.y, p4.z, p4.w};
#pragma unroll
            for (int t = 0; t < 4; t++) {
                int r = rBase + kk + t;
                if (r > R - 1) r = R - 1;       // p=0 there; clamp avoids OOB
                float2 v2 = *(float2*)(Vs + r * 66 + d0);
                o0 += pv[t] * v2.x;
                o1 += pv[t] * v2.y;
            }
        }
        float inv = 1.f / lloc;
        *(__half2*)(O + base + (size_t)i * D + d0) =
            __halves2half2(__float2half_rn(o0 * inv), __float2half_rn(o1 * inv));
    }
}

// Dense row i = T-1: 8 warps partition keys (2-way unrolled), log-sum-exp merge.
__global__ void __launch_bounds__(256) attn_last_kernel(
    const float* __restrict__ Q, const float* __restrict__ K,
    const float* __restrict__ V, half* __restrict__ O)
{
    int lane = threadIdx.x & 31;
    int warp = threadIdx.x >> 5;
    int h = blockIdx.x, b = blockIdx.y;
    const int i = T - 1;

    size_t base = (size_t)b * T * D + h * HD;
    const float* qp = Q + base + (size_t)i * D;
    float q0 = qp[lane] * 0.125f, q1 = qp[lane + 32] * 0.125f;

    float m = -1e30f, l = 0.f, o0 = 0.f, o1 = 0.f;
    for (int j = warp; j < T; j += 16) {
        const float* kpa = K + base + (size_t)j * D;
        const float* kpb = kpa + (size_t)8 * D;
        float sa = q0 * kpa[lane] + q1 * kpa[lane + 32];
        float sb = q0 * kpb[lane] + q1 * kpb[lane + 32];
#pragma unroll
        for (int o = 16; o > 0; o >>= 1) {
            sa += __shfl_xor_sync(0xffffffffu, sa, o);
            sb += __shfl_xor_sync(0xffffffffu, sb, o);
        }
        float nm = fmaxf(m, fmaxf(sa, sb));
        float scx = __expf(m - nm);
        float pa = __expf(sa - nm);
        float pb = __expf(sb - nm);
        const float* vpa = V + base + (size_t)j * D;
        const float* vpb = vpa + (size_t)8 * D;
        l  = l  * scx + pa + pb;
        o0 = o0 * scx + pa * vpa[lane] + pb * vpb[lane];
        o1 = o1 * scx + pa * vpa[lane + 32] + pb * vpb[lane + 32];
        m = nm;
    }
    __shared__ float sm[8], sl[8], so[8][64];
    if (lane == 0) { sm[warp] = m; sl[warp] = l; }
    so[warp][lane] = o0; so[warp][lane + 32] = o1;
    __syncthreads();
    if (warp == 0) {
        float gm = -1e30f;
#pragma unroll
        for (int w = 0; w < 8; w++) gm = fmaxf(gm, sm[w]);
        float gl = 0.f, a0 = 0.f, a1 = 0.f;
#pragma unroll
        for (int w = 0; w < 8; w++) {
            float scx = __expf(sm[w] - gm);
            gl += scx * sl[w];
            a0 += scx * so[w][lane];
            a1 += scx * so[w][lane + 32];
        }
        float inv = 1.f / gl;
        size_t oidx = base + (size_t)i * D;
        O[oidx + lane]      = __float2half_rn(a0 * inv);
        O[oidx + lane + 32] = __float2half_rn(a1 * inv);
    }
}

// ---------------- launch ----------------
extern "C" void kernel_launch(void* const* d_in, const int* in_sizes, int n_in,
                              void* d_out, int out_size)
{
    const float* x    = (const float*)d_in[0];
    const float* ln1g = (const float*)d_in[1];
    const float* ln1b = (const float*)d_in[2];
    const float* ln2g = (const float*)d_in[3];
    const float* ln2b = (const float*)d_in[4];
    const float* Wq   = (const float*)d_in[5];
    const float* Wk   = (const float*)d_in[6];
    const float* Wv   = (const float*)d_in[7];
    const float* Wo   = (const float*)d_in[8];
    const float* bo   = (const float*)d_in[9];
    const float* W1   = (const float*)d_in[10];
    const float* b1   = (const float*)d_in[11];
    const float* W2   = (const float*)d_in[12];
    const float* b2   = (const float*)d_in[13];
    float* out = (float*)d_out;

    cudaFuncSetAttribute(mm_kernel,  cudaFuncAttributeMaxDynamicSharedMemorySize, MM_SMEM);
    cudaFuncSetAttribute(qkv_kernel, cudaFuncAttributeMaxDynamicSharedMemorySize, MM_SMEM);
    cudaFuncSetAttribute(attn_tile_kernel, cudaFuncAttributeMaxDynamicSharedMemorySize, ATTN_SMEM);

    float *q, *k, *v, *x2;
    half *hA, *aA, *h2A, *f1A;
    half *WqT, *WkT, *WvT, *WoT, *W1T, *W2T;
    cudaGetSymbolAddress((void**)&q,   g_q);
    cudaGetSymbolAddress((void**)&k,   g_k);
    cudaGetSymbolAddress((void**)&v,   g_v);
    cudaGetSymbolAddress((void**)&x2,  g_x2);
    cudaGetSymbolAddress((void**)&hA,  g_h);
    cudaGetSymbolAddress((void**)&aA,  g_a);
    cudaGetSymbolAddress((void**)&h2A, g_h2);
    cudaGetSymbolAddress((void**)&f1A, g_f1);
    cudaGetSymbolAddress((void**)&WqT, g_WqT);
    cudaGetSymbolAddress((void**)&WkT, g_WkT);
    cudaGetSymbolAddress((void**)&WvT, g_WvT);
    cudaGetSymbolAddress((void**)&WoT, g_WoT);
    cudaGetSymbolAddress((void**)&W1T, g_W1T);
    cudaGetSymbolAddress((void**)&W2T, g_W2T);

    dim3 tb(32, 8);
    tcvt4_kernel<<<dim3(D / 32, D / 32, 4), tb>>>(Wq, WqT, Wk, WkT, Wv, WvT, Wo, WoT);
    tcvt_kernel<<<dim3(DFF / 32, D / 32), tb>>>(W1, W1T, D, DFF);
    tcvt_kernel<<<dim3(D / 32, DFF / 32), tb>>>(W2, W2T, DFF, D);

    // 1. h = LN1(x)
    ln_kernel<<<NT, 256>>>(x, ln1g, ln1b, hA);

    // 2. fused QKV
    qkv_kernel<<<dim3(24, NT / 256), 256, MM_SMEM>>>(hA, WqT, q, WkT, k, WvT, v);

    // 3. attention
    attn_tile_kernel<<<dim3(T / 64, NH, Bsz), 256, ATTN_SMEM>>>(q, k, v, aA);
    attn_last_kernel<<<dim3(NH, Bsz), 256>>>(q, k, v, aA);

    // 4. x2 = x + att @ Wo + bo
    dim3 gD(D / 128, NT / 256);
    mm_kernel<<<gD, 256, MM_SMEM>>>(aA, WoT, bo, x, x2, nullptr, D, D, 0);

    // 5. h2 = LN2(x2)
    ln_kernel<<<NT, 256>>>(x2, ln2g, ln2b, h2A);

    // 6. f1 = gelu(h2 @ W1 + b1)
    dim3 gF(DFF / 128, NT / 256);
    mm_kernel<<<gF, 256, MM_SMEM>>>(h2A, W1T, b1, nullptr, nullptr, f1A, D, DFF, 1);

    // 7. out = x2 + f1 @ W2 + b2
    mm_kernel<<<gD, 256, MM_SMEM>>>(f1A, W2T, b2, x2, out, nullptr, DFF, D, 0);
}